// round 4
// baseline (speedup 1.0000x reference)
#include <cuda_runtime.h>
#include <math.h>

#define T_TOK 8192
#define DD    128
#define MM    64

typedef unsigned long long ull;

// ---------------- scratch ----------------------------------------------------
__device__ float g_cbuf[T_TOK * MM];      // c[t][m]
__device__ float g_uT[DD * MM];           // [d][m]
__device__ float g_WgT[DD * MM];          // [d][m]
__device__ float g_bveff[MM];
__device__ float g_bc[MM * DD];           // bt + char
__device__ float g_Wtil[65 * DD * DD];    // Wtil[m] = Wt[m]@Wi_bot ; m=64 -> Wi_top
__device__ float g_bctil[65 * DD];        // bctil[m] = bc[m]@Wi_bot ; m=64 -> bi

// ---------------- f32x2 helpers ----------------------------------------------
__device__ __forceinline__ ull pack2(float a, float b) {
    ull r;
    asm("mov.b64 %0, {%1, %2};" : "=l"(r) : "r"(__float_as_uint(a)), "r"(__float_as_uint(b)));
    return r;
}
__device__ __forceinline__ ull fma2(ull a, ull b, ull c) {
    ull d;
    asm("fma.rn.f32x2 %0, %1, %2, %3;" : "=l"(d) : "l"(a), "l"(b), "l"(c));
    return d;
}
__device__ __forceinline__ ull add2(ull a, ull b) {
    ull d;
    asm("add.rn.f32x2 %0, %1, %2;" : "=l"(d) : "l"(a), "l"(b));
    return d;
}
__device__ __forceinline__ float2 unpack2(ull v) {
    float2 r;
    asm("mov.b64 {%0, %1}, %2;" : "=f"(r.x), "=f"(r.y) : "l"(v));
    return r;
}
union F4U2 { float4 f; ull u[2]; };

// ---------------- ka1: bc, WgT, bveff, uT -------------------------------------
__global__ void __launch_bounds__(128) ka1(
    const float* __restrict__ Wt, const float* __restrict__ bt,
    const float* __restrict__ chr, const float* __restrict__ Wg,
    const float* __restrict__ Wv, const float* __restrict__ bv)
{
    int m = blockIdx.x, tid = threadIdx.x;
    int lane = tid & 31, warp = tid >> 5;
    __shared__ float red[4];

    float wv  = Wv[m * DD + tid];
    float bcv = bt[m * DD + tid] + chr[m * DD + tid];
    g_bc[m * DD + tid]  = bcv;
    g_WgT[tid * MM + m] = Wg[m * DD + tid];

    float v = bcv * wv;
    #pragma unroll
    for (int o = 16; o > 0; o >>= 1) v += __shfl_down_sync(0xffffffffu, v, o);
    if (lane == 0) red[warp] = v;
    __syncthreads();
    if (tid == 0) g_bveff[m] = bv[m] + red[0] + red[1] + red[2] + red[3];

    const float4* W4 = (const float4*)Wt + (size_t)m * 4096;
    float4 wv4 = ((const float4*)(Wv + m * DD))[lane];
    for (int r = warp; r < DD; r += 8) {
        float4 w0 = W4[r * 32 + lane];
        float4 w1 = W4[(r + 4) * 32 + lane];
        float a0 = w0.x * wv4.x + w0.y * wv4.y + w0.z * wv4.z + w0.w * wv4.w;
        float a1 = w1.x * wv4.x + w1.y * wv4.y + w1.z * wv4.z + w1.w * wv4.w;
        #pragma unroll
        for (int o = 16; o > 0; o >>= 1) {
            a0 += __shfl_down_sync(0xffffffffu, a0, o);
            a1 += __shfl_down_sync(0xffffffffu, a1, o);
        }
        if (lane == 0) {
            g_uT[r * MM + m]       = a0;
            g_uT[(r + 4) * MM + m] = a1;
        }
    }
}

// ---------------- ka2: Wtil = Wt@Wi_bot, bctil = bc@Wi_bot, +Wi_top copy ------
__global__ void __launch_bounds__(128) ka2(
    const float* __restrict__ Wt, const float* __restrict__ Wi,
    const float* __restrict__ bi)
{
    int bid = blockIdx.x;
    int m = bid >> 2, dq = bid & 3, j = threadIdx.x;

    if (m == 64) {  // copy Wi_top / bi
        #pragma unroll 4
        for (int d = 0; d < 32; ++d)
            g_Wtil[64 * 16384 + (dq * 32 + d) * DD + j] = Wi[(dq * 32 + d) * DD + j];
        if (dq == 0) g_bctil[64 * DD + j] = bi[j];
        return;
    }

    __shared__ float ws[33][129];
    #pragma unroll
    for (int k = 0; k < 32; ++k) {
        int idx = j + k * 128;
        int d = idx >> 7, e = idx & 127;
        ws[d][e] = Wt[(size_t)(m * DD + dq * 32 + d) * DD + e];
    }
    if (dq == 0) ws[32][j] = g_bc[m * DD + j];
    __syncthreads();

    float acc[32];
    #pragma unroll
    for (int d = 0; d < 32; ++d) acc[d] = 0.f;
    float accb = 0.f;

    for (int e = 0; e < 128; ++e) {
        float wi = Wi[(128 + e) * DD + j];
        #pragma unroll
        for (int d = 0; d < 32; ++d) acc[d] = fmaf(ws[d][e], wi, acc[d]);
        if (dq == 0) accb = fmaf(ws[32][e], wi, accb);
    }
    #pragma unroll
    for (int d = 0; d < 32; ++d)
        g_Wtil[m * 16384 + (dq * 32 + d) * DD + j] = acc[d];
    if (dq == 0) g_bctil[m * DD + j] = accb;
}

// ---------------- kb: selector / c / victory ----------------------------------
// 16 tokens per block, 256 threads. sind[col][tok]: PLAIN floats, tokens
// contiguous (stride 18 floats keeps &sind[i][2q] 8-byte aligned so LDS.64
// reads deliver the token pair (v_{2q}, v_{2q+1}) for f32x2 math).
__global__ void __launch_bounds__(256) kb_selector(
    const float* __restrict__ x, const float* __restrict__ ctx,
    const float* __restrict__ W1, const float* __restrict__ b1,
    const float* __restrict__ W2, const float* __restrict__ b2,
    const float* __restrict__ O,  const float* __restrict__ bg,
    float* __restrict__ out)
{
    __shared__ float sind[256][18];
    __shared__ float hs[16][256];
    __shared__ float ls[16][64];
    __shared__ float vs[16][64];

    int t0 = blockIdx.x * 16;
    int tid = threadIdx.x;

    #pragma unroll
    for (int k = 0; k < 16; ++k) {
        int idx = tid + k * 256;
        int tok = idx >> 8, col = idx & 255;
        float v = (col < 128) ? x[(size_t)(t0 + tok) * DD + col]
                              : ctx[(size_t)(t0 + tok) * DD + (col - 128)];
        sind[col][tok] = v;
    }
    __syncthreads();

    // h = gelu(sel_in @ W1 + b1): f32x2 over token pairs, thread owns column j
    {
        int j = tid;
        float bj = b1[j];
        ull acc8[8];
        ull bb = pack2(bj, bj);
        #pragma unroll
        for (int q = 0; q < 8; ++q) acc8[q] = bb;
        for (int i = 0; i < 256; ++i) {
            float w = W1[i * 256 + j];
            ull wq = pack2(w, w);
            #pragma unroll
            for (int q = 0; q < 8; ++q) {
                ull xp = *(const ull*)&sind[i][2 * q];
                acc8[q] = fma2(xp, wq, acc8[q]);
            }
        }
        #pragma unroll
        for (int q = 0; q < 8; ++q) {
            float2 v = unpack2(acc8[q]);
            hs[2 * q][j]     = 0.5f * v.x * (1.0f + erff(v.x * 0.70710678118654752f));
            hs[2 * q + 1][j] = 0.5f * v.y * (1.0f + erff(v.y * 0.70710678118654752f));
        }
    }
    __syncthreads();

    int n  = tid & 63;
    int tq = tid >> 6;
    int tb = tq * 4;

    // logits = h @ W2 + b2
    {
        float acc[4];
        float bn = b2[n];
        #pragma unroll
        for (int q = 0; q < 4; ++q) acc[q] = bn;
        for (int j = 0; j < 256; ++j) {
            float w = W2[j * 64 + n];
            #pragma unroll
            for (int q = 0; q < 4; ++q) acc[q] = fmaf(hs[tb + q][j], w, acc[q]);
        }
        #pragma unroll
        for (int q = 0; q < 4; ++q) ls[tb + q][n] = acc[q];
    }
    __syncthreads();

    if (tid < 16) {
        float mx = -1e30f;
        #pragma unroll
        for (int k = 0; k < 64; ++k) mx = fmaxf(mx, ls[tid][k]);
        float s = 0.f;
        #pragma unroll
        for (int k = 0; k < 64; ++k) { float e = expf(ls[tid][k] - mx); ls[tid][k] = e; s += e; }
        float inv = 1.0f / s;
        #pragma unroll
        for (int k = 0; k < 64; ++k) ls[tid][k] *= inv;
    }
    __syncthreads();

    // timing / victory / gates / c ; thread owns mechanism n for 4 tokens
    {
        float ta[4], va[4], gl[4];
        float tb0 = bg[n], vb0 = g_bveff[n];
        #pragma unroll
        for (int q = 0; q < 4; ++q) { ta[q] = tb0; va[q] = vb0; gl[q] = 0.f; }
        for (int d = 0; d < DD; ++d) {
            float wg = g_WgT[d * MM + n];
            float wu = g_uT[d * MM + n];
            #pragma unroll
            for (int q = 0; q < 4; ++q) {
                float xv = sind[d][tb + q];
                ta[q] = fmaf(xv, wg, ta[q]);
                va[q] = fmaf(xv, wu, va[q]);
            }
        }
        for (int mm = 0; mm < MM; ++mm) {
            float o = O[mm * MM + n];
            #pragma unroll
            for (int q = 0; q < 4; ++q) gl[q] = fmaf(ls[tb + q][mm], o, gl[q]);
        }
        #pragma unroll
        for (int q = 0; q < 4; ++q) {
            float sc     = ls[tb + q][n];
            float timing = 1.0f / (1.0f + expf(-ta[q]));
            float vic    = 1.0f / (1.0f + expf(-va[q]));
            float gate   = 1.0f + tanhf(gl[q]);
            g_cbuf[(size_t)(t0 + tb + q) * MM + n] = timing * gate * sc;
            vs[tb + q][n] = vic * sc;
        }
    }
    __syncthreads();

    if (tid < 16) {
        float s = 0.f;
        #pragma unroll
        for (int k = 0; k < 64; ++k) s += vs[tid][k];
        out[(size_t)T_TOK * DD + t0 + tid] = s;
    }
}

// ---------------- kc: uniform 65-mechanism fused GEMM -------------------------
// 32 tokens x 128 e per block; thread: eg=tid&15 -> 8 e (4 pairs), tg=tid>>4 -> 4 toks
__global__ void __launch_bounds__(128, 2) kc_main(
    const float* __restrict__ x, float* __restrict__ out)
{
    __shared__ float2 xs[128][33];   // [d][tok] duplicated (v,v)
    __shared__ float  csf[65][33];   // c[m][tok]; row 64 = 1.0

    int t0  = blockIdx.x * 32;
    int tid = threadIdx.x;

    #pragma unroll
    for (int k = 0; k < 32; ++k) {
        int idx = tid + k * 128;
        int tok = idx >> 7, d = idx & 127;
        float v = x[(size_t)(t0 + tok) * DD + d];
        xs[d][tok] = make_float2(v, v);
    }
    #pragma unroll
    for (int k = 0; k < 16; ++k) {
        int idx = tid + k * 128;
        int tok = idx >> 6, m = idx & 63;
        csf[m][tok] = g_cbuf[(size_t)(t0 + tok) * MM + m];
    }
    if (tid < 32) csf[64][tid] = 1.0f;
    __syncthreads();

    int eg = tid & 15, tg = tid >> 4;
    int e0 = eg * 8, tb = tg * 4;

    ull acc[4][4];
    #pragma unroll
    for (int i = 0; i < 4; ++i)
        #pragma unroll
        for (int p = 0; p < 4; ++p) acc[i][p] = 0ULL;

    for (int m = 0; m < 65; ++m) {
        ull y[4][4];
        #pragma unroll
        for (int i = 0; i < 4; ++i)
            #pragma unroll
            for (int p = 0; p < 4; ++p) y[i][p] = 0ULL;

        const float4* W = (const float4*)(g_Wtil + (size_t)m * 16384) + eg * 2;
        #pragma unroll 4
        for (int d = 0; d < 128; ++d) {
            F4U2 wa, wb;
            wa.f = W[d * 32];
            wb.f = W[d * 32 + 1];
            ull xp[4];
            #pragma unroll
            for (int p = 0; p < 4; ++p)
                xp[p] = *(const ull*)&xs[d][tb + p];
            #pragma unroll
            for (int p = 0; p < 4; ++p) {
                y[0][p] = fma2(xp[p], wa.u[0], y[0][p]);
                y[1][p] = fma2(xp[p], wa.u[1], y[1][p]);
                y[2][p] = fma2(xp[p], wb.u[0], y[2][p]);
                y[3][p] = fma2(xp[p], wb.u[1], y[3][p]);
            }
        }

        F4U2 ba, bbv;
        ba.f  = ((const float4*)(g_bctil + m * DD))[eg * 2];
        bbv.f = ((const float4*)(g_bctil + m * DD))[eg * 2 + 1];
        ull cp[4];
        #pragma unroll
        for (int p = 0; p < 4; ++p) {
            float c = csf[m][tb + p];
            cp[p] = pack2(c, c);
        }
        #pragma unroll
        for (int p = 0; p < 4; ++p) {
            acc[0][p] = fma2(add2(y[0][p], ba.u[0]),  cp[p], acc[0][p]);
            acc[1][p] = fma2(add2(y[1][p], ba.u[1]),  cp[p], acc[1][p]);
            acc[2][p] = fma2(add2(y[2][p], bbv.u[0]), cp[p], acc[2][p]);
            acc[3][p] = fma2(add2(y[3][p], bbv.u[1]), cp[p], acc[3][p]);
        }
    }

    #pragma unroll
    for (int p = 0; p < 4; ++p) {
        float2 r0 = unpack2(acc[0][p]);
        float2 r1 = unpack2(acc[1][p]);
        float2 r2 = unpack2(acc[2][p]);
        float2 r3 = unpack2(acc[3][p]);
        float4 lo = make_float4(r0.x, r0.y, r1.x, r1.y);
        float4 hi = make_float4(r2.x, r2.y, r3.x, r3.y);
        *(float4*)&out[(size_t)(t0 + tb + p) * DD + e0]     = lo;
        *(float4*)&out[(size_t)(t0 + tb + p) * DD + e0 + 4] = hi;
    }
}

// ---------------- launch ------------------------------------------------------
extern "C" void kernel_launch(void* const* d_in, const int* in_sizes, int n_in,
                              void* d_out, int out_size)
{
    const float* x    = (const float*)d_in[0];
    const float* ctx  = (const float*)d_in[1];
    const float* Wt   = (const float*)d_in[2];
    const float* bt   = (const float*)d_in[3];
    const float* chr  = (const float*)d_in[4];
    const float* Wg   = (const float*)d_in[5];
    const float* bg   = (const float*)d_in[6];
    const float* Wv   = (const float*)d_in[7];
    const float* bv   = (const float*)d_in[8];
    const float* O    = (const float*)d_in[9];
    const float* W1   = (const float*)d_in[10];
    const float* b1   = (const float*)d_in[11];
    const float* W2   = (const float*)d_in[12];
    const float* b2   = (const float*)d_in[13];
    const float* Wi   = (const float*)d_in[14];
    const float* bi   = (const float*)d_in[15];
    float* out = (float*)d_out;

    ka1<<<64, 128>>>(Wt, bt, chr, Wg, Wv, bv);
    ka2<<<260, 128>>>(Wt, Wi, bi);
    kb_selector<<<T_TOK / 16, 256>>>(x, ctx, W1, b1, W2, b2, O, bg, out);
    kc_main<<<T_TOK / 32, 128>>>(x, out);
}

// round 5
// speedup vs baseline: 1.0869x; 1.0869x over previous
#include <cuda_runtime.h>
#include <math.h>

#define T_TOK 8192
#define DD    128
#define MM    64

typedef unsigned long long ull;

// ---------------- scratch ----------------------------------------------------
__device__ float g_cbuf[T_TOK * MM];      // c[t][m]
__device__ float g_uT[DD * MM];           // [d][m]
__device__ float g_WgT[DD * MM];          // [d][m]
__device__ float g_bveff[MM];
__device__ float g_bc[MM * DD];           // bt + char
__device__ float g_Wtil[65 * DD * DD];    // Wtil[m] = Wt[m]@Wi_bot ; m=64 -> Wi_top
__device__ float g_bctil[65 * DD];        // bctil[m] = bc[m]@Wi_bot ; m=64 -> bi
__device__ float g_part[2 * T_TOK * DD];  // m-split partial outputs

// ---------------- f32x2 helpers ----------------------------------------------
__device__ __forceinline__ ull pack2(float a, float b) {
    ull r;
    asm("mov.b64 %0, {%1, %2};" : "=l"(r) : "r"(__float_as_uint(a)), "r"(__float_as_uint(b)));
    return r;
}
__device__ __forceinline__ ull fma2(ull a, ull b, ull c) {
    ull d;
    asm("fma.rn.f32x2 %0, %1, %2, %3;" : "=l"(d) : "l"(a), "l"(b), "l"(c));
    return d;
}
__device__ __forceinline__ ull add2(ull a, ull b) {
    ull d;
    asm("add.rn.f32x2 %0, %1, %2;" : "=l"(d) : "l"(a), "l"(b));
    return d;
}
__device__ __forceinline__ float2 unpack2(ull v) {
    float2 r;
    asm("mov.b64 {%0, %1}, %2;" : "=f"(r.x), "=f"(r.y) : "l"(v));
    return r;
}
union F4U2 { float4 f; ull u[2]; };

// ---------------- ka1: bc, WgT, bveff, uT -------------------------------------
__global__ void __launch_bounds__(128) ka1(
    const float* __restrict__ Wt, const float* __restrict__ bt,
    const float* __restrict__ chr, const float* __restrict__ Wg,
    const float* __restrict__ Wv, const float* __restrict__ bv)
{
    int m = blockIdx.x, tid = threadIdx.x;
    int lane = tid & 31, warp = tid >> 5;
    __shared__ float red[4];

    float wv  = Wv[m * DD + tid];
    float bcv = bt[m * DD + tid] + chr[m * DD + tid];
    g_bc[m * DD + tid]  = bcv;
    g_WgT[tid * MM + m] = Wg[m * DD + tid];

    float v = bcv * wv;
    #pragma unroll
    for (int o = 16; o > 0; o >>= 1) v += __shfl_down_sync(0xffffffffu, v, o);
    if (lane == 0) red[warp] = v;
    __syncthreads();
    if (tid == 0) g_bveff[m] = bv[m] + red[0] + red[1] + red[2] + red[3];

    const float4* W4 = (const float4*)Wt + (size_t)m * 4096;
    float4 wv4 = ((const float4*)(Wv + m * DD))[lane];
    for (int r = warp; r < DD; r += 8) {
        float4 w0 = W4[r * 32 + lane];
        float4 w1 = W4[(r + 4) * 32 + lane];
        float a0 = w0.x * wv4.x + w0.y * wv4.y + w0.z * wv4.z + w0.w * wv4.w;
        float a1 = w1.x * wv4.x + w1.y * wv4.y + w1.z * wv4.z + w1.w * wv4.w;
        #pragma unroll
        for (int o = 16; o > 0; o >>= 1) {
            a0 += __shfl_down_sync(0xffffffffu, a0, o);
            a1 += __shfl_down_sync(0xffffffffu, a1, o);
        }
        if (lane == 0) {
            g_uT[r * MM + m]       = a0;
            g_uT[(r + 4) * MM + m] = a1;
        }
    }
}

// ---------------- ka2: Wtil = Wt@Wi_bot, bctil = bc@Wi_bot, +Wi_top copy ------
__global__ void __launch_bounds__(128) ka2(
    const float* __restrict__ Wt, const float* __restrict__ Wi,
    const float* __restrict__ bi)
{
    int bid = blockIdx.x;
    int m = bid >> 2, dq = bid & 3, j = threadIdx.x;

    if (m == 64) {
        #pragma unroll 4
        for (int d = 0; d < 32; ++d)
            g_Wtil[64 * 16384 + (dq * 32 + d) * DD + j] = Wi[(dq * 32 + d) * DD + j];
        if (dq == 0) g_bctil[64 * DD + j] = bi[j];
        return;
    }

    __shared__ float ws[33][129];
    #pragma unroll
    for (int k = 0; k < 32; ++k) {
        int idx = j + k * 128;
        int d = idx >> 7, e = idx & 127;
        ws[d][e] = Wt[(size_t)(m * DD + dq * 32 + d) * DD + e];
    }
    if (dq == 0) ws[32][j] = g_bc[m * DD + j];
    __syncthreads();

    float acc[32];
    #pragma unroll
    for (int d = 0; d < 32; ++d) acc[d] = 0.f;
    float accb = 0.f;

    for (int e = 0; e < 128; ++e) {
        float wi = Wi[(128 + e) * DD + j];
        #pragma unroll
        for (int d = 0; d < 32; ++d) acc[d] = fmaf(ws[d][e], wi, acc[d]);
        if (dq == 0) accb = fmaf(ws[32][e], wi, accb);
    }
    #pragma unroll
    for (int d = 0; d < 32; ++d)
        g_Wtil[m * 16384 + (dq * 32 + d) * DD + j] = acc[d];
    if (dq == 0) g_bctil[m * DD + j] = accb;
}

// ---------------- kb: selector / c / victory ----------------------------------
__global__ void __launch_bounds__(256) kb_selector(
    const float* __restrict__ x, const float* __restrict__ ctx,
    const float* __restrict__ W1, const float* __restrict__ b1,
    const float* __restrict__ W2, const float* __restrict__ b2,
    const float* __restrict__ O,  const float* __restrict__ bg,
    float* __restrict__ out)
{
    __shared__ float sind[256][18];
    __shared__ float hs[16][256];
    __shared__ float ls[16][64];
    __shared__ float vs[16][64];

    int t0 = blockIdx.x * 16;
    int tid = threadIdx.x;

    #pragma unroll
    for (int k = 0; k < 16; ++k) {
        int idx = tid + k * 256;
        int tok = idx >> 8, col = idx & 255;
        float v = (col < 128) ? x[(size_t)(t0 + tok) * DD + col]
                              : ctx[(size_t)(t0 + tok) * DD + (col - 128)];
        sind[col][tok] = v;
    }
    __syncthreads();

    // h = gelu(sel_in @ W1 + b1): f32x2 over token pairs
    {
        int j = tid;
        float bj = b1[j];
        ull acc8[8];
        ull bb = pack2(bj, bj);
        #pragma unroll
        for (int q = 0; q < 8; ++q) acc8[q] = bb;
        for (int i = 0; i < 256; ++i) {
            float w = W1[i * 256 + j];
            ull wq = pack2(w, w);
            #pragma unroll
            for (int q = 0; q < 8; ++q) {
                ull xp = *(const ull*)&sind[i][2 * q];
                acc8[q] = fma2(xp, wq, acc8[q]);
            }
        }
        #pragma unroll
        for (int q = 0; q < 8; ++q) {
            float2 v = unpack2(acc8[q]);
            hs[2 * q][j]     = 0.5f * v.x * (1.0f + erff(v.x * 0.70710678118654752f));
            hs[2 * q + 1][j] = 0.5f * v.y * (1.0f + erff(v.y * 0.70710678118654752f));
        }
    }
    __syncthreads();

    int n  = tid & 63;
    int tq = tid >> 6;
    int tb = tq * 4;

    {
        float acc[4];
        float bn = b2[n];
        #pragma unroll
        for (int q = 0; q < 4; ++q) acc[q] = bn;
        for (int j = 0; j < 256; ++j) {
            float w = W2[j * 64 + n];
            #pragma unroll
            for (int q = 0; q < 4; ++q) acc[q] = fmaf(hs[tb + q][j], w, acc[q]);
        }
        #pragma unroll
        for (int q = 0; q < 4; ++q) ls[tb + q][n] = acc[q];
    }
    __syncthreads();

    if (tid < 16) {
        float mx = -1e30f;
        #pragma unroll
        for (int k = 0; k < 64; ++k) mx = fmaxf(mx, ls[tid][k]);
        float s = 0.f;
        #pragma unroll
        for (int k = 0; k < 64; ++k) { float e = expf(ls[tid][k] - mx); ls[tid][k] = e; s += e; }
        float inv = 1.0f / s;
        #pragma unroll
        for (int k = 0; k < 64; ++k) ls[tid][k] *= inv;
    }
    __syncthreads();

    {
        float ta[4], va[4], gl[4];
        float tb0 = bg[n], vb0 = g_bveff[n];
        #pragma unroll
        for (int q = 0; q < 4; ++q) { ta[q] = tb0; va[q] = vb0; gl[q] = 0.f; }
        for (int d = 0; d < DD; ++d) {
            float wg = g_WgT[d * MM + n];
            float wu = g_uT[d * MM + n];
            #pragma unroll
            for (int q = 0; q < 4; ++q) {
                float xv = sind[d][tb + q];
                ta[q] = fmaf(xv, wg, ta[q]);
                va[q] = fmaf(xv, wu, va[q]);
            }
        }
        for (int mm = 0; mm < MM; ++mm) {
            float o = O[mm * MM + n];
            #pragma unroll
            for (int q = 0; q < 4; ++q) gl[q] = fmaf(ls[tb + q][mm], o, gl[q]);
        }
        #pragma unroll
        for (int q = 0; q < 4; ++q) {
            float sc     = ls[tb + q][n];
            float timing = 1.0f / (1.0f + expf(-ta[q]));
            float vic    = 1.0f / (1.0f + expf(-va[q]));
            float gate   = 1.0f + tanhf(gl[q]);
            g_cbuf[(size_t)(t0 + tb + q) * MM + n] = timing * gate * sc;
            vs[tb + q][n] = vic * sc;
        }
    }
    __syncthreads();

    if (tid < 16) {
        float s = 0.f;
        #pragma unroll
        for (int k = 0; k < 64; ++k) s += vs[tid][k];
        out[(size_t)T_TOK * DD + t0 + tid] = s;
    }
}

// ---------------- kc: m-split fused GEMM --------------------------------------
// grid (256, 2): 32 tokens x 128 e per block; blockIdx.y selects m range.
// thread: eg=tid&15 -> 8 e (4 f32x2 e-pairs); tg=tid>>4 -> 4 tokens.
__global__ void __launch_bounds__(128, 4) kc_main(
    const float* __restrict__ x)
{
    __shared__ float xs[128][33];    // [d][tok] plain
    __shared__ float csf[65][33];    // c[m][tok]; row 64 = 1.0

    int t0  = blockIdx.x * 32;
    int grp = blockIdx.y;
    int m0  = grp * 32;
    int m1  = grp ? 65 : 32;
    int tid = threadIdx.x;

    #pragma unroll
    for (int k = 0; k < 32; ++k) {
        int idx = tid + k * 128;
        int tok = idx >> 7, d = idx & 127;
        xs[d][tok] = x[(size_t)(t0 + tok) * DD + d];
    }
    #pragma unroll
    for (int k = 0; k < 16; ++k) {
        int idx = tid + k * 128;
        int tok = idx >> 6, m = idx & 63;
        csf[m][tok] = g_cbuf[(size_t)(t0 + tok) * MM + m];
    }
    if (tid < 32) csf[64][tid] = 1.0f;
    __syncthreads();

    int eg = tid & 15, tg = tid >> 4;
    int e0 = eg * 8, tb = tg * 4;

    ull acc[4][4];
    #pragma unroll
    for (int i = 0; i < 4; ++i)
        #pragma unroll
        for (int p = 0; p < 4; ++p) acc[i][p] = 0ULL;

    for (int m = m0; m < m1; ++m) {
        ull y[4][4];
        #pragma unroll
        for (int i = 0; i < 4; ++i)
            #pragma unroll
            for (int p = 0; p < 4; ++p) y[i][p] = 0ULL;

        const float4* W = (const float4*)(g_Wtil + (size_t)m * 16384) + eg * 2;
        #pragma unroll 2
        for (int d = 0; d < 128; ++d) {
            F4U2 wa, wb;
            wa.f = W[d * 32];
            wb.f = W[d * 32 + 1];
            ull xp[4];
            #pragma unroll
            for (int p = 0; p < 4; ++p) {
                float v = xs[d][tb + p];
                xp[p] = pack2(v, v);
            }
            #pragma unroll
            for (int p = 0; p < 4; ++p) {
                y[0][p] = fma2(xp[p], wa.u[0], y[0][p]);
                y[1][p] = fma2(xp[p], wa.u[1], y[1][p]);
                y[2][p] = fma2(xp[p], wb.u[0], y[2][p]);
                y[3][p] = fma2(xp[p], wb.u[1], y[3][p]);
            }
        }

        F4U2 ba, bbv;
        ba.f  = ((const float4*)(g_bctil + m * DD))[eg * 2];
        bbv.f = ((const float4*)(g_bctil + m * DD))[eg * 2 + 1];
        ull cp[4];
        #pragma unroll
        for (int p = 0; p < 4; ++p) {
            float c = csf[m][tb + p];
            cp[p] = pack2(c, c);
        }
        #pragma unroll
        for (int p = 0; p < 4; ++p) {
            acc[0][p] = fma2(add2(y[0][p], ba.u[0]),  cp[p], acc[0][p]);
            acc[1][p] = fma2(add2(y[1][p], ba.u[1]),  cp[p], acc[1][p]);
            acc[2][p] = fma2(add2(y[2][p], bbv.u[0]), cp[p], acc[2][p]);
            acc[3][p] = fma2(add2(y[3][p], bbv.u[1]), cp[p], acc[3][p]);
        }
    }

    float* part = g_part + (size_t)grp * T_TOK * DD;
    #pragma unroll
    for (int p = 0; p < 4; ++p) {
        float2 r0 = unpack2(acc[0][p]);
        float2 r1 = unpack2(acc[1][p]);
        float2 r2 = unpack2(acc[2][p]);
        float2 r3 = unpack2(acc[3][p]);
        float4 lo = make_float4(r0.x, r0.y, r1.x, r1.y);
        float4 hi = make_float4(r2.x, r2.y, r3.x, r3.y);
        *(float4*)&part[(size_t)(t0 + tb + p) * DD + e0]     = lo;
        *(float4*)&part[(size_t)(t0 + tb + p) * DD + e0 + 4] = hi;
    }
}

// ---------------- kd: combine partials ----------------------------------------
__global__ void __launch_bounds__(256) kd_combine(float* __restrict__ out)
{
    int i = blockIdx.x * 256 + threadIdx.x;     // float4 index
    const float4* p0 = (const float4*)g_part;
    const float4* p1 = (const float4*)(g_part + (size_t)T_TOK * DD);
    float4 a = p0[i], b = p1[i];
    float4 r = make_float4(a.x + b.x, a.y + b.y, a.z + b.z, a.w + b.w);
    ((float4*)out)[i] = r;
}

// ---------------- launch ------------------------------------------------------
extern "C" void kernel_launch(void* const* d_in, const int* in_sizes, int n_in,
                              void* d_out, int out_size)
{
    const float* x    = (const float*)d_in[0];
    const float* ctx  = (const float*)d_in[1];
    const float* Wt   = (const float*)d_in[2];
    const float* bt   = (const float*)d_in[3];
    const float* chr  = (const float*)d_in[4];
    const float* Wg   = (const float*)d_in[5];
    const float* bg   = (const float*)d_in[6];
    const float* Wv   = (const float*)d_in[7];
    const float* bv   = (const float*)d_in[8];
    const float* O    = (const float*)d_in[9];
    const float* W1   = (const float*)d_in[10];
    const float* b1   = (const float*)d_in[11];
    const float* W2   = (const float*)d_in[12];
    const float* b2   = (const float*)d_in[13];
    const float* Wi   = (const float*)d_in[14];
    const float* bi   = (const float*)d_in[15];
    float* out = (float*)d_out;

    ka1<<<64, 128>>>(Wt, bt, chr, Wg, Wv, bv);
    ka2<<<260, 128>>>(Wt, Wi, bi);
    kb_selector<<<T_TOK / 16, 256>>>(x, ctx, W1, b1, W2, b2, O, bg, out);
    kc_main<<<dim3(T_TOK / 32, 2), 128>>>(x);
    kd_combine<<<(T_TOK * DD / 4) / 256, 256>>>(out);
}

// round 6
// speedup vs baseline: 1.2912x; 1.1880x over previous
#include <cuda_runtime.h>
#include <math.h>

#define T_TOK 8192
#define DD    128
#define MM    64
#define MSPLIT 4

typedef unsigned long long ull;

// ---------------- scratch ----------------------------------------------------
__device__ float g_cbuf[T_TOK * MM];      // c[t][m]
__device__ float g_uT[DD * MM];           // [d][m]
__device__ float g_WgT[DD * MM];          // [d][m]
__device__ float g_bveff[MM];
__device__ float g_bc[MM * DD];           // bt + char
__device__ float g_Wtil[65 * DD * DD];    // Wtil[m] = Wt[m]@Wi_bot ; m=64 -> Wi_top
__device__ float g_bctil[65 * DD];        // bctil[m] = bc[m]@Wi_bot ; m=64 -> bi
__device__ float g_part[MSPLIT * T_TOK * DD];

// ---------------- f32x2 helpers ----------------------------------------------
__device__ __forceinline__ ull pack2(float a, float b) {
    ull r;
    asm("mov.b64 %0, {%1, %2};" : "=l"(r) : "r"(__float_as_uint(a)), "r"(__float_as_uint(b)));
    return r;
}
__device__ __forceinline__ ull fma2(ull a, ull b, ull c) {
    ull d;
    asm("fma.rn.f32x2 %0, %1, %2, %3;" : "=l"(d) : "l"(a), "l"(b), "l"(c));
    return d;
}
__device__ __forceinline__ ull add2(ull a, ull b) {
    ull d;
    asm("add.rn.f32x2 %0, %1, %2;" : "=l"(d) : "l"(a), "l"(b));
    return d;
}
__device__ __forceinline__ float2 unpack2(ull v) {
    float2 r;
    asm("mov.b64 {%0, %1}, %2;" : "=f"(r.x), "=f"(r.y) : "l"(v));
    return r;
}
union F4U2 { float4 f; ull u[2]; };

// ---------------- ka1: bc, WgT, bveff, uT -------------------------------------
__global__ void __launch_bounds__(128) ka1(
    const float* __restrict__ Wt, const float* __restrict__ bt,
    const float* __restrict__ chr, const float* __restrict__ Wg,
    const float* __restrict__ Wv, const float* __restrict__ bv)
{
    int m = blockIdx.x, tid = threadIdx.x;
    int lane = tid & 31, warp = tid >> 5;
    __shared__ float red[4];

    float wv  = Wv[m * DD + tid];
    float bcv = bt[m * DD + tid] + chr[m * DD + tid];
    g_bc[m * DD + tid]  = bcv;
    g_WgT[tid * MM + m] = Wg[m * DD + tid];

    float v = bcv * wv;
    #pragma unroll
    for (int o = 16; o > 0; o >>= 1) v += __shfl_down_sync(0xffffffffu, v, o);
    if (lane == 0) red[warp] = v;
    __syncthreads();
    if (tid == 0) g_bveff[m] = bv[m] + red[0] + red[1] + red[2] + red[3];

    const float4* W4 = (const float4*)Wt + (size_t)m * 4096;
    float4 wv4 = ((const float4*)(Wv + m * DD))[lane];
    for (int r = warp; r < DD; r += 8) {
        float4 w0 = W4[r * 32 + lane];
        float4 w1 = W4[(r + 4) * 32 + lane];
        float a0 = w0.x * wv4.x + w0.y * wv4.y + w0.z * wv4.z + w0.w * wv4.w;
        float a1 = w1.x * wv4.x + w1.y * wv4.y + w1.z * wv4.z + w1.w * wv4.w;
        #pragma unroll
        for (int o = 16; o > 0; o >>= 1) {
            a0 += __shfl_down_sync(0xffffffffu, a0, o);
            a1 += __shfl_down_sync(0xffffffffu, a1, o);
        }
        if (lane == 0) {
            g_uT[r * MM + m]       = a0;
            g_uT[(r + 4) * MM + m] = a1;
        }
    }
}

// ---------------- ka2: Wtil = Wt@Wi_bot, bctil = bc@Wi_bot, +Wi_top copy ------
__global__ void __launch_bounds__(128) ka2(
    const float* __restrict__ Wt, const float* __restrict__ Wi,
    const float* __restrict__ bi)
{
    int bid = blockIdx.x;
    int m = bid >> 2, dq = bid & 3, j = threadIdx.x;

    if (m == 64) {
        #pragma unroll 4
        for (int d = 0; d < 32; ++d)
            g_Wtil[64 * 16384 + (dq * 32 + d) * DD + j] = Wi[(dq * 32 + d) * DD + j];
        if (dq == 0) g_bctil[64 * DD + j] = bi[j];
        return;
    }

    __shared__ float ws[33][129];
    #pragma unroll
    for (int k = 0; k < 32; ++k) {
        int idx = j + k * 128;
        int d = idx >> 7, e = idx & 127;
        ws[d][e] = Wt[(size_t)(m * DD + dq * 32 + d) * DD + e];
    }
    if (dq == 0) ws[32][j] = g_bc[m * DD + j];
    __syncthreads();

    float acc[32];
    #pragma unroll
    for (int d = 0; d < 32; ++d) acc[d] = 0.f;
    float accb = 0.f;

    for (int e = 0; e < 128; ++e) {
        float wi = Wi[(128 + e) * DD + j];
        #pragma unroll
        for (int d = 0; d < 32; ++d) acc[d] = fmaf(ws[d][e], wi, acc[d]);
        if (dq == 0) accb = fmaf(ws[32][e], wi, accb);
    }
    #pragma unroll
    for (int d = 0; d < 32; ++d)
        g_Wtil[m * 16384 + (dq * 32 + d) * DD + j] = acc[d];
    if (dq == 0) g_bctil[m * DD + j] = accb;
}

// ---------------- kb: selector / c / victory ----------------------------------
__global__ void __launch_bounds__(256) kb_selector(
    const float* __restrict__ x, const float* __restrict__ ctx,
    const float* __restrict__ W1, const float* __restrict__ b1,
    const float* __restrict__ W2, const float* __restrict__ b2,
    const float* __restrict__ O,  const float* __restrict__ bg,
    float* __restrict__ out)
{
    __shared__ float sind[256][18];
    __shared__ float hs[16][256];
    __shared__ float ls[16][64];
    __shared__ float vs[16][64];

    int t0 = blockIdx.x * 16;
    int tid = threadIdx.x;

    #pragma unroll
    for (int k = 0; k < 16; ++k) {
        int idx = tid + k * 256;
        int tok = idx >> 8, col = idx & 255;
        float v = (col < 128) ? x[(size_t)(t0 + tok) * DD + col]
                              : ctx[(size_t)(t0 + tok) * DD + (col - 128)];
        sind[col][tok] = v;
    }
    __syncthreads();

    {
        int j = tid;
        float bj = b1[j];
        ull acc8[8];
        ull bb = pack2(bj, bj);
        #pragma unroll
        for (int q = 0; q < 8; ++q) acc8[q] = bb;
        for (int i = 0; i < 256; ++i) {
            float w = W1[i * 256 + j];
            ull wq = pack2(w, w);
            #pragma unroll
            for (int q = 0; q < 8; ++q) {
                ull xp = *(const ull*)&sind[i][2 * q];
                acc8[q] = fma2(xp, wq, acc8[q]);
            }
        }
        #pragma unroll
        for (int q = 0; q < 8; ++q) {
            float2 v = unpack2(acc8[q]);
            hs[2 * q][j]     = 0.5f * v.x * (1.0f + erff(v.x * 0.70710678118654752f));
            hs[2 * q + 1][j] = 0.5f * v.y * (1.0f + erff(v.y * 0.70710678118654752f));
        }
    }
    __syncthreads();

    int n  = tid & 63;
    int tq = tid >> 6;
    int tb = tq * 4;

    {
        float acc[4];
        float bn = b2[n];
        #pragma unroll
        for (int q = 0; q < 4; ++q) acc[q] = bn;
        for (int j = 0; j < 256; ++j) {
            float w = W2[j * 64 + n];
            #pragma unroll
            for (int q = 0; q < 4; ++q) acc[q] = fmaf(hs[tb + q][j], w, acc[q]);
        }
        #pragma unroll
        for (int q = 0; q < 4; ++q) ls[tb + q][n] = acc[q];
    }
    __syncthreads();

    if (tid < 16) {
        float mx = -1e30f;
        #pragma unroll
        for (int k = 0; k < 64; ++k) mx = fmaxf(mx, ls[tid][k]);
        float s = 0.f;
        #pragma unroll
        for (int k = 0; k < 64; ++k) { float e = expf(ls[tid][k] - mx); ls[tid][k] = e; s += e; }
        float inv = 1.0f / s;
        #pragma unroll
        for (int k = 0; k < 64; ++k) ls[tid][k] *= inv;
    }
    __syncthreads();

    {
        float ta[4], va[4], gl[4];
        float tb0 = bg[n], vb0 = g_bveff[n];
        #pragma unroll
        for (int q = 0; q < 4; ++q) { ta[q] = tb0; va[q] = vb0; gl[q] = 0.f; }
        for (int d = 0; d < DD; ++d) {
            float wg = g_WgT[d * MM + n];
            float wu = g_uT[d * MM + n];
            #pragma unroll
            for (int q = 0; q < 4; ++q) {
                float xv = sind[d][tb + q];
                ta[q] = fmaf(xv, wg, ta[q]);
                va[q] = fmaf(xv, wu, va[q]);
            }
        }
        for (int mm = 0; mm < MM; ++mm) {
            float o = O[mm * MM + n];
            #pragma unroll
            for (int q = 0; q < 4; ++q) gl[q] = fmaf(ls[tb + q][mm], o, gl[q]);
        }
        #pragma unroll
        for (int q = 0; q < 4; ++q) {
            float sc     = ls[tb + q][n];
            float timing = 1.0f / (1.0f + expf(-ta[q]));
            float vic    = 1.0f / (1.0f + expf(-va[q]));
            float gate   = 1.0f + tanhf(gl[q]);
            g_cbuf[(size_t)(t0 + tb + q) * MM + n] = timing * gate * sc;
            vs[tb + q][n] = vic * sc;
        }
    }
    __syncthreads();

    if (tid < 16) {
        float s = 0.f;
        #pragma unroll
        for (int k = 0; k < 64; ++k) s += vs[tid][k];
        out[(size_t)T_TOK * DD + t0 + tid] = s;
    }
}

// ---------------- kc: token-pair-lane fused GEMM, m-split 4 -------------------
// grid (256, 4), block 128. Tile: 32 tokens x 128 e.
// Thread: eg=tid&31 -> 4 e-cols (one LDG.128 of weights per d);
//         tg=tid>>5 -> 8 tokens as 4 f32x2 token-pairs (2 broadcast LDS.128).
__global__ void __launch_bounds__(128, 5) kc_main(
    const float* __restrict__ x)
{
    __shared__ float xs[128][36];    // [d][tok]
    __shared__ float cs[65][36];     // [m][tok]; row 64 = 1.0

    int t0  = blockIdx.x * 32;
    int grp = blockIdx.y;
    int m0  = (grp * 65) / MSPLIT;
    int m1  = ((grp + 1) * 65) / MSPLIT;
    int tid = threadIdx.x;

    #pragma unroll
    for (int k = 0; k < 32; ++k) {
        int idx = tid + k * 128;
        int tok = idx >> 7, d = idx & 127;
        xs[d][tok] = x[(size_t)(t0 + tok) * DD + d];
    }
    #pragma unroll
    for (int k = 0; k < 16; ++k) {
        int idx = tid + k * 128;
        int tok = idx >> 6, m = idx & 63;
        cs[m][tok] = g_cbuf[(size_t)(t0 + tok) * MM + m];
    }
    if (tid < 32) cs[64][tid] = 1.0f;
    __syncthreads();

    int eg = tid & 31, tg = tid >> 5;
    int e0 = eg * 4, tb = tg * 8;

    ull acc[4][4];   // [e][token-pair]
    #pragma unroll
    for (int i = 0; i < 4; ++i)
        #pragma unroll
        for (int p = 0; p < 4; ++p) acc[i][p] = 0ULL;

    for (int m = m0; m < m1; ++m) {
        ull y[4][4];
        #pragma unroll
        for (int i = 0; i < 4; ++i)
            #pragma unroll
            for (int p = 0; p < 4; ++p) y[i][p] = 0ULL;

        const float4* W = (const float4*)(g_Wtil + (size_t)m * 16384) + eg;
        #pragma unroll 2
        for (int d = 0; d < 128; ++d) {
            float4 w = W[d * 32];                 // 4 e-cols of weights
            ull wd[4];
            wd[0] = pack2(w.x, w.x); wd[1] = pack2(w.y, w.y);
            wd[2] = pack2(w.z, w.z); wd[3] = pack2(w.w, w.w);
            F4U2 xa, xb;                          // 8 tokens = 4 pairs
            xa.f = *(const float4*)&xs[d][tb];
            xb.f = *(const float4*)&xs[d][tb + 4];
            ull xp[4] = { xa.u[0], xa.u[1], xb.u[0], xb.u[1] };
            #pragma unroll
            for (int i = 0; i < 4; ++i)
                #pragma unroll
                for (int p = 0; p < 4; ++p)
                    y[i][p] = fma2(xp[p], wd[i], y[i][p]);
        }

        float4 b4 = ((const float4*)(g_bctil + m * DD))[eg];
        ull bd[4];
        bd[0] = pack2(b4.x, b4.x); bd[1] = pack2(b4.y, b4.y);
        bd[2] = pack2(b4.z, b4.z); bd[3] = pack2(b4.w, b4.w);
        F4U2 ca, cb;
        ca.f = *(const float4*)&cs[m][tb];
        cb.f = *(const float4*)&cs[m][tb + 4];
        ull cp[4] = { ca.u[0], ca.u[1], cb.u[0], cb.u[1] };
        #pragma unroll
        for (int i = 0; i < 4; ++i)
            #pragma unroll
            for (int p = 0; p < 4; ++p)
                acc[i][p] = fma2(add2(y[i][p], bd[i]), cp[p], acc[i][p]);
    }

    float* part = g_part + (size_t)grp * T_TOK * DD;
    #pragma unroll
    for (int p = 0; p < 4; ++p) {
        float2 v0 = unpack2(acc[0][p]);
        float2 v1 = unpack2(acc[1][p]);
        float2 v2 = unpack2(acc[2][p]);
        float2 v3 = unpack2(acc[3][p]);
        float4 r0 = make_float4(v0.x, v1.x, v2.x, v3.x);
        float4 r1 = make_float4(v0.y, v1.y, v2.y, v3.y);
        *(float4*)&part[(size_t)(t0 + tb + 2 * p) * DD + e0]     = r0;
        *(float4*)&part[(size_t)(t0 + tb + 2 * p + 1) * DD + e0] = r1;
    }
}

// ---------------- kd: combine partials ----------------------------------------
__global__ void __launch_bounds__(256) kd_combine(float* __restrict__ out)
{
    int i = blockIdx.x * 256 + threadIdx.x;     // float4 index
    const float4* p0 = (const float4*)g_part;
    const float4* p1 = (const float4*)(g_part + (size_t)T_TOK * DD);
    const float4* p2 = (const float4*)(g_part + (size_t)2 * T_TOK * DD);
    const float4* p3 = (const float4*)(g_part + (size_t)3 * T_TOK * DD);
    float4 a = p0[i], b = p1[i], c = p2[i], d = p3[i];
    float4 r = make_float4(a.x + b.x + c.x + d.x,
                           a.y + b.y + c.y + d.y,
                           a.z + b.z + c.z + d.z,
                           a.w + b.w + c.w + d.w);
    ((float4*)out)[i] = r;
}

// ---------------- launch ------------------------------------------------------
extern "C" void kernel_launch(void* const* d_in, const int* in_sizes, int n_in,
                              void* d_out, int out_size)
{
    const float* x    = (const float*)d_in[0];
    const float* ctx  = (const float*)d_in[1];
    const float* Wt   = (const float*)d_in[2];
    const float* bt   = (const float*)d_in[3];
    const float* chr  = (const float*)d_in[4];
    const float* Wg   = (const float*)d_in[5];
    const float* bg   = (const float*)d_in[6];
    const float* Wv   = (const float*)d_in[7];
    const float* bv   = (const float*)d_in[8];
    const float* O    = (const float*)d_in[9];
    const float* W1   = (const float*)d_in[10];
    const float* b1   = (const float*)d_in[11];
    const float* W2   = (const float*)d_in[12];
    const float* b2   = (const float*)d_in[13];
    const float* Wi   = (const float*)d_in[14];
    const float* bi   = (const float*)d_in[15];
    float* out = (float*)d_out;

    ka1<<<64, 128>>>(Wt, bt, chr, Wg, Wv, bv);
    ka2<<<260, 128>>>(Wt, Wi, bi);
    kb_selector<<<T_TOK / 16, 256>>>(x, ctx, W1, b1, W2, b2, O, bg, out);
    kc_main<<<dim3(T_TOK / 32, MSPLIT), 128>>>(x);
    kd_combine<<<(T_TOK * DD / 4) / 256, 256>>>(out);
}

// round 8
// speedup vs baseline: 2.9753x; 2.3043x over previous
#include <cuda_runtime.h>
#include <cuda_bf16.h>
#include <math.h>

#define T_TOK 8192
#define DD    128
#define MM    64
#define GROUPS 5
#define NMG   13          // mechanisms per group (5*13 = 65)

typedef unsigned long long ull;
typedef unsigned int u32;
typedef unsigned short u16;

// ---------------- scratch ----------------------------------------------------
__device__ float g_cbuf[T_TOK * MM];        // c[t][m]
__device__ float g_uT[DD * MM];
__device__ float g_WgT[DD * MM];
__device__ float g_bveff[MM];
__device__ float g_bc[MM * DD];             // bt + char
__device__ float g_bct[65 * DD];            // bctil[m] ; m=64 -> bi
__device__ u32   g_Bpk[65 * 16384];         // W frag-packed: [m][ks(8)][ntile(16)][lane(32)][hi0,hi1,lo0,lo1]
__device__ float g_part[GROUPS * T_TOK * DD];

// ---------------- helpers ------------------------------------------------------
__device__ __forceinline__ u32 smem_u32(const void* p) {
    u32 a;
    asm("{ .reg .u64 t; cvta.to.shared.u64 t, %1; cvt.u32.u64 %0, t; }" : "=r"(a) : "l"(p));
    return a;
}
__device__ __forceinline__ void mma_bf16(float* c, const u32* a, const u32* b) {
    asm volatile("mma.sync.aligned.m16n8k16.row.col.f32.bf16.bf16.f32 "
        "{%0,%1,%2,%3}, {%4,%5,%6,%7}, {%8,%9}, {%0,%1,%2,%3};"
        : "+f"(c[0]), "+f"(c[1]), "+f"(c[2]), "+f"(c[3])
        : "r"(a[0]), "r"(a[1]), "r"(a[2]), "r"(a[3]), "r"(b[0]), "r"(b[1]));
}
__device__ __forceinline__ void ldsm4(u32* r, u32 addr) {
    asm volatile("ldmatrix.sync.aligned.m8n8.x4.shared.b16 {%0,%1,%2,%3}, [%4];"
        : "=r"(r[0]), "=r"(r[1]), "=r"(r[2]), "=r"(r[3]) : "r"(addr));
}
__device__ __forceinline__ void lds128(u32* r, u32 addr) {
    asm volatile("ld.shared.v4.u32 {%0,%1,%2,%3}, [%4];"
        : "=r"(r[0]), "=r"(r[1]), "=r"(r[2]), "=r"(r[3]) : "r"(addr));
}
__device__ __forceinline__ void cp16(u32 dst, const void* src) {
    asm volatile("cp.async.cg.shared.global [%0], [%1], 16;" :: "r"(dst), "l"(src) : "memory");
}
__device__ __forceinline__ void split_bf16(float v, u16& h, u16& l) {
    __nv_bfloat16 hb = __float2bfloat16_rn(v);
    float r = v - __bfloat162float(hb);
    h = __bfloat16_as_ushort(hb);
    l = __bfloat16_as_ushort(__float2bfloat16_rn(r));
}

// ---------------- ka1: bc, WgT, bveff, uT -------------------------------------
__global__ void __launch_bounds__(128) ka1(
    const float* __restrict__ Wt, const float* __restrict__ bt,
    const float* __restrict__ chr, const float* __restrict__ Wg,
    const float* __restrict__ Wv, const float* __restrict__ bv)
{
    int m = blockIdx.x, tid = threadIdx.x;
    int lane = tid & 31, warp = tid >> 5;
    __shared__ float red[4];

    float wv  = Wv[m * DD + tid];
    float bcv = bt[m * DD + tid] + chr[m * DD + tid];
    g_bc[m * DD + tid]  = bcv;
    g_WgT[tid * MM + m] = Wg[m * DD + tid];

    float v = bcv * wv;
    #pragma unroll
    for (int o = 16; o > 0; o >>= 1) v += __shfl_down_sync(0xffffffffu, v, o);
    if (lane == 0) red[warp] = v;
    __syncthreads();
    if (tid == 0) g_bveff[m] = bv[m] + red[0] + red[1] + red[2] + red[3];

    const float4* W4 = (const float4*)Wt + (size_t)m * 4096;
    float4 wv4 = ((const float4*)(Wv + m * DD))[lane];
    for (int r = warp; r < DD; r += 8) {
        float4 w0 = W4[r * 32 + lane];
        float4 w1 = W4[(r + 4) * 32 + lane];
        float a0 = w0.x * wv4.x + w0.y * wv4.y + w0.z * wv4.z + w0.w * wv4.w;
        float a1 = w1.x * wv4.x + w1.y * wv4.y + w1.z * wv4.z + w1.w * wv4.w;
        #pragma unroll
        for (int o = 16; o > 0; o >>= 1) {
            a0 += __shfl_down_sync(0xffffffffu, a0, o);
            a1 += __shfl_down_sync(0xffffffffu, a1, o);
        }
        if (lane == 0) {
            g_uT[r * MM + m]       = a0;
            g_uT[(r + 4) * MM + m] = a1;
        }
    }
}

// ---------------- ka2: Wtil = Wt@Wi_bot -> fragment-packed bf16 hi/lo ----------
// Fragment layout for mma.m16n8k16 B (col-major, n=e, k=d):
//   lane = (e%8)*4 + (d%8)/2 ; reg = (d%16)/8 ; pair (d even, d+1) packed in u32.
// Per-lane 16B vector: [hi_reg0, hi_reg1, lo_reg0, lo_reg1].
__global__ void __launch_bounds__(128) ka2(
    const float* __restrict__ Wt, const float* __restrict__ Wi,
    const float* __restrict__ bi)
{
    int bid = blockIdx.x;
    int m = bid >> 2, dq = bid & 3, j = threadIdx.x;   // j = e
    u32* buf = g_Bpk + (size_t)m * 16384;

    float acc[32];

    if (m == 64) {   // Wi_top: B(e,d) = Wi[d][e]
        #pragma unroll 4
        for (int dd = 0; dd < 32; ++dd)
            acc[dd] = Wi[(dq * 32 + dd) * DD + j];
        if (dq == 0) g_bct[64 * DD + j] = bi[j];
    } else {
        __shared__ float ws[33][129];
        #pragma unroll
        for (int k = 0; k < 32; ++k) {
            int idx = j + k * 128;
            int d = idx >> 7, e = idx & 127;
            ws[d][e] = Wt[(size_t)(m * DD + dq * 32 + d) * DD + e];
        }
        if (dq == 0) ws[32][j] = g_bc[m * DD + j];
        __syncthreads();

        #pragma unroll
        for (int d = 0; d < 32; ++d) acc[d] = 0.f;
        float accb = 0.f;
        for (int e = 0; e < 128; ++e) {
            float wi = Wi[(128 + e) * DD + j];
            #pragma unroll
            for (int d = 0; d < 32; ++d) acc[d] = fmaf(ws[d][e], wi, acc[d]);
            if (dq == 0) accb = fmaf(ws[32][e], wi, accb);
        }
        if (dq == 0) g_bct[m * DD + j] = accb;
    }

    // pack pairs into fragment layout
    int ntile = j >> 3;
    #pragma unroll
    for (int dd = 0; dd < 32; dd += 2) {
        int d = dq * 32 + dd;
        u16 h0, l0, h1, l1;
        split_bf16(acc[dd], h0, l0);
        split_bf16(acc[dd + 1], h1, l1);
        u32 hw = (u32)h0 | ((u32)h1 << 16);
        u32 lw = (u32)l0 | ((u32)l1 << 16);
        int lane = (j & 7) * 4 + ((d & 7) >> 1);
        int ks = d >> 4;
        int rh = (d >> 3) & 1;
        u32* v = buf + (((ks * 16) + ntile) * 32 + lane) * 4;
        v[rh]     = hw;
        v[2 + rh] = lw;
    }
}

// ---------------- kb: selector / c / victory ----------------------------------
__global__ void __launch_bounds__(256) kb_selector(
    const float* __restrict__ x, const float* __restrict__ ctx,
    const float* __restrict__ W1, const float* __restrict__ b1,
    const float* __restrict__ W2, const float* __restrict__ b2,
    const float* __restrict__ O,  const float* __restrict__ bg,
    float* __restrict__ out)
{
    __shared__ float sind[256][18];
    __shared__ float hs[16][256];
    __shared__ float ls[16][64];
    __shared__ float vs[16][64];

    int t0 = blockIdx.x * 16;
    int tid = threadIdx.x;

    #pragma unroll
    for (int k = 0; k < 16; ++k) {
        int idx = tid + k * 256;
        int tok = idx >> 8, col = idx & 255;
        float v = (col < 128) ? x[(size_t)(t0 + tok) * DD + col]
                              : ctx[(size_t)(t0 + tok) * DD + (col - 128)];
        sind[col][tok] = v;
    }
    __syncthreads();

    {
        int j = tid;
        float acc[16];
        float bj = b1[j];
        #pragma unroll
        for (int q = 0; q < 16; ++q) acc[q] = bj;
        for (int i = 0; i < 256; ++i) {
            float w = W1[i * 256 + j];
            #pragma unroll
            for (int q = 0; q < 16; ++q) acc[q] = fmaf(sind[i][q], w, acc[q]);
        }
        #pragma unroll
        for (int q = 0; q < 16; ++q)
            hs[q][j] = 0.5f * acc[q] * (1.0f + erff(acc[q] * 0.70710678118654752f));
    }
    __syncthreads();

    int n  = tid & 63;
    int tq = tid >> 6;
    int tb = tq * 4;

    {
        float acc[4];
        float bn = b2[n];
        #pragma unroll
        for (int q = 0; q < 4; ++q) acc[q] = bn;
        for (int j = 0; j < 256; ++j) {
            float w = W2[j * 64 + n];
            #pragma unroll
            for (int q = 0; q < 4; ++q) acc[q] = fmaf(hs[tb + q][j], w, acc[q]);
        }
        #pragma unroll
        for (int q = 0; q < 4; ++q) ls[tb + q][n] = acc[q];
    }
    __syncthreads();

    if (tid < 16) {
        float mx = -1e30f;
        #pragma unroll
        for (int k = 0; k < 64; ++k) mx = fmaxf(mx, ls[tid][k]);
        float s = 0.f;
        #pragma unroll
        for (int k = 0; k < 64; ++k) { float e = expf(ls[tid][k] - mx); ls[tid][k] = e; s += e; }
        float inv = 1.0f / s;
        #pragma unroll
        for (int k = 0; k < 64; ++k) ls[tid][k] *= inv;
    }
    __syncthreads();

    {
        float ta[4], va[4], gl[4];
        float tb0 = bg[n], vb0 = g_bveff[n];
        #pragma unroll
        for (int q = 0; q < 4; ++q) { ta[q] = tb0; va[q] = vb0; gl[q] = 0.f; }
        for (int d = 0; d < DD; ++d) {
            float wg = g_WgT[d * MM + n];
            float wu = g_uT[d * MM + n];
            #pragma unroll
            for (int q = 0; q < 4; ++q) {
                float xv = sind[d][tb + q];
                ta[q] = fmaf(xv, wg, ta[q]);
                va[q] = fmaf(xv, wu, va[q]);
            }
        }
        for (int mm = 0; mm < MM; ++mm) {
            float o = O[mm * MM + n];
            #pragma unroll
            for (int q = 0; q < 4; ++q) gl[q] = fmaf(ls[tb + q][mm], o, gl[q]);
        }
        #pragma unroll
        for (int q = 0; q < 4; ++q) {
            float sc     = ls[tb + q][n];
            float timing = 1.0f / (1.0f + expf(-ta[q]));
            float vic    = 1.0f / (1.0f + expf(-va[q]));
            float gate   = 1.0f + tanhf(gl[q]);
            g_cbuf[(size_t)(t0 + tb + q) * MM + n] = timing * gate * sc;
            vs[tb + q][n] = vic * sc;
        }
    }
    __syncthreads();

    if (tid < 16) {
        float s = 0.f;
        #pragma unroll
        for (int k = 0; k < 64; ++k) s += vs[tid][k];
        out[(size_t)T_TOK * DD + t0 + tid] = s;
    }
}

// ---------------- kc: mma.sync bf16-split fused GEMM --------------------------
// grid (128 token-tiles, GROUPS), 512 threads = 16 warps.
// Block tile: 64 tokens x 128 e. Warp tile 16 x 32: warp_m = wid&3, warp_n = wid>>2.
#define APAD     136                      // bf16 elems per A row (128 + 8 pad)
#define OFF_W    0                        // 2 stages x 64KB
#define OFF_AHI  131072                   // 64*272 = 17408
#define OFF_ALO  148480
#define OFF_CS   165888                   // 13*64*4 = 3328
#define OFF_BCT  169216                   // 13*128*4 = 6656
#define SMEM_KC  175872

__global__ void __launch_bounds__(512, 1) kc_mma(const float* __restrict__ x)
{
    extern __shared__ __align__(16) char smem[];
    u32 sbase = smem_u32(smem);
    float* cs_s  = (float*)(smem + OFF_CS);
    float* bct_s = (float*)(smem + OFF_BCT);

    int tid  = threadIdx.x;
    int lane = tid & 31, wid = tid >> 5;
    int wm = wid & 3, wn = wid >> 2;           // warp token-tile, warp e-tile
    int t0 = blockIdx.x * 64;
    int m0 = blockIdx.y * NMG;

    // c + bct tiles
    for (int i = tid; i < NMG * 64; i += 512) {
        int mi = i >> 6, r = i & 63;
        int gm = m0 + mi;
        cs_s[i] = (gm == 64) ? 1.0f : g_cbuf[(size_t)(t0 + r) * MM + gm];
    }
    for (int i = tid; i < NMG * 128; i += 512) {
        int mi = i >> 7, r = i & 127;
        bct_s[i] = g_bct[(m0 + mi) * DD + r];
    }

    // A: convert X[64 x 128] to bf16 hi/lo in smem (padded rows)
    {
        u16* ah = (u16*)(smem + OFF_AHI);
        u16* al = (u16*)(smem + OFF_ALO);
        #pragma unroll
        for (int r = 0; r < 4; ++r) {
            int idx = tid + r * 512;          // float4 index over 64x32
            int tok = idx >> 5, dq = idx & 31;
            float4 v = ((const float4*)(x + (size_t)(t0 + tok) * DD))[dq];
            u16 h[4], l[4];
            split_bf16(v.x, h[0], l[0]); split_bf16(v.y, h[1], l[1]);
            split_bf16(v.z, h[2], l[2]); split_bf16(v.w, h[3], l[3]);
            int o = tok * APAD + dq * 4;
            *(uint2*)&ah[o] = make_uint2((u32)h[0] | ((u32)h[1] << 16), (u32)h[2] | ((u32)h[3] << 16));
            *(uint2*)&al[o] = make_uint2((u32)l[0] | ((u32)l[1] << 16), (u32)l[2] | ((u32)l[3] << 16));
        }
    }

    // prefetch W[m0] into stage 0
    {
        const char* src = (const char*)g_Bpk + (size_t)m0 * 65536;
        #pragma unroll
        for (int r = 0; r < 8; ++r) {
            int idx = tid + r * 512;
            cp16(sbase + OFF_W + idx * 16, src + (size_t)idx * 16);
        }
        asm volatile("cp.async.commit_group;" ::: "memory");
    }

    // per-warp A addresses for ldmatrix
    u32 aoff = (u32)((wm * 16 + (lane & 15)) * (APAD * 2) + (lane >> 4) * 16);
    u32 ahiA = sbase + OFF_AHI + aoff;
    u32 aloA = sbase + OFF_ALO + aoff;

    float accF[4][4];
    #pragma unroll
    for (int nt = 0; nt < 4; ++nt)
        #pragma unroll
        for (int j = 0; j < 4; ++j) accF[nt][j] = 0.f;

    int rb = wm * 16 + (lane >> 2);           // token row base within block
    int cb = wn * 32 + 2 * (lane & 3);        // e col base within block

    for (int mi = 0; mi < NMG; ++mi) {
        int s = mi & 1;
        if (mi + 1 < NMG) {
            const char* src = (const char*)g_Bpk + (size_t)(m0 + mi + 1) * 65536;
            u32 dst = sbase + OFF_W + (s ^ 1) * 65536;
            #pragma unroll
            for (int r = 0; r < 8; ++r) {
                int idx = tid + r * 512;
                cp16(dst + idx * 16, src + (size_t)idx * 16);
            }
            asm volatile("cp.async.commit_group;" ::: "memory");
            asm volatile("cp.async.wait_group 1;" ::: "memory");
        } else {
            asm volatile("cp.async.wait_group 0;" ::: "memory");
        }
        __syncthreads();

        float accY[4][4];
        #pragma unroll
        for (int nt = 0; nt < 4; ++nt)
            #pragma unroll
            for (int j = 0; j < 4; ++j) accY[nt][j] = 0.f;

        u32 wbase = sbase + OFF_W + s * 65536;
        #pragma unroll
        for (int ks = 0; ks < 8; ++ks) {
            u32 ah[4], al[4];
            ldsm4(ah, ahiA + ks * 32);
            ldsm4(al, aloA + ks * 32);
            #pragma unroll
            for (int nt = 0; nt < 4; ++nt) {
                u32 b4[4];
                lds128(b4, wbase + (((ks * 16) + wn * 4 + nt) * 32 + lane) * 16);
                mma_bf16(accY[nt], ah, b4);        // hi*hi
                mma_bf16(accY[nt], ah, b4 + 2);    // hi*lo
                mma_bf16(accY[nt], al, b4);        // lo*hi
            }
        }

        // epilogue: accF += c * (Y + bct)
        float c0 = cs_s[mi * 64 + rb];
        float c1 = cs_s[mi * 64 + rb + 8];
        #pragma unroll
        for (int nt = 0; nt < 4; ++nt) {
            float2 bb = *(const float2*)&bct_s[mi * 128 + cb + nt * 8];
            accF[nt][0] = fmaf(c0, accY[nt][0] + bb.x, accF[nt][0]);
            accF[nt][1] = fmaf(c0, accY[nt][1] + bb.y, accF[nt][1]);
            accF[nt][2] = fmaf(c1, accY[nt][2] + bb.x, accF[nt][2]);
            accF[nt][3] = fmaf(c1, accY[nt][3] + bb.y, accF[nt][3]);
        }
        __syncthreads();
    }

    // write partial
    float* part = g_part + (size_t)blockIdx.y * T_TOK * DD;
    #pragma unroll
    for (int nt = 0; nt < 4; ++nt) {
        int col = cb + nt * 8;
        *(float2*)&part[(size_t)(t0 + rb) * DD + col]     = make_float2(accF[nt][0], accF[nt][1]);
        *(float2*)&part[(size_t)(t0 + rb + 8) * DD + col] = make_float2(accF[nt][2], accF[nt][3]);
    }
}

// ---------------- kd: combine GROUPS partials ----------------------------------
__global__ void __launch_bounds__(256) kd_combine(float* __restrict__ out)
{
    int i = blockIdx.x * 256 + threadIdx.x;
    float4 r = make_float4(0.f, 0.f, 0.f, 0.f);
    #pragma unroll
    for (int g = 0; g < GROUPS; ++g) {
        float4 a = ((const float4*)(g_part + (size_t)g * T_TOK * DD))[i];
        r.x += a.x; r.y += a.y; r.z += a.z; r.w += a.w;
    }
    ((float4*)out)[i] = r;
}

// ---------------- launch ------------------------------------------------------
extern "C" void kernel_launch(void* const* d_in, const int* in_sizes, int n_in,
                              void* d_out, int out_size)
{
    const float* x    = (const float*)d_in[0];
    const float* ctx  = (const float*)d_in[1];
    const float* Wt   = (const float*)d_in[2];
    const float* bt   = (const float*)d_in[3];
    const float* chr  = (const float*)d_in[4];
    const float* Wg   = (const float*)d_in[5];
    const float* bg   = (const float*)d_in[6];
    const float* Wv   = (const float*)d_in[7];
    const float* bv   = (const float*)d_in[8];
    const float* O    = (const float*)d_in[9];
    const float* W1   = (const float*)d_in[10];
    const float* b1   = (const float*)d_in[11];
    const float* W2   = (const float*)d_in[12];
    const float* b2   = (const float*)d_in[13];
    const float* Wi   = (const float*)d_in[14];
    const float* bi   = (const float*)d_in[15];
    float* out = (float*)d_out;

    cudaFuncSetAttribute(kc_mma, cudaFuncAttributeMaxDynamicSharedMemorySize, SMEM_KC);

    ka1<<<64, 128>>>(Wt, bt, chr, Wg, Wv, bv);
    ka2<<<260, 128>>>(Wt, Wi, bi);
    kb_selector<<<T_TOK / 16, 256>>>(x, ctx, W1, b1, W2, b2, O, bg, out);
    kc_mma<<<dim3(T_TOK / 64, GROUPS), 512, SMEM_KC>>>(x);
    kd_combine<<<(T_TOK * DD / 4) / 256, 256>>>(out);
}

// round 9
// speedup vs baseline: 3.1911x; 1.0725x over previous
#include <cuda_runtime.h>
#include <cuda_bf16.h>
#include <math.h>

#define T_TOK 8192
#define DD    128
#define MM    64
#define GROUPS 5
#define NMG   13          // mechanisms per group (5*13 = 65)

typedef unsigned long long ull;
typedef unsigned int u32;
typedef unsigned short u16;

// ---------------- scratch ----------------------------------------------------
__device__ float g_cbuf[T_TOK * MM];        // c[t][m]
__device__ float g_uT[DD * MM];
__device__ float g_WgT[DD * MM];
__device__ float g_bveff[MM];
__device__ float g_bc[MM * DD];             // bt + char
__device__ float g_bct[65 * DD];            // bctil[m] ; m=64 -> bi
__device__ u32   g_Bpk[65 * 16384];         // W frag-packed: [m][ks(8)][ntile(16)][lane(32)][hi0,hi1,lo0,lo1]
__device__ float g_part[GROUPS * T_TOK * DD];

// ---------------- helpers ------------------------------------------------------
__device__ __forceinline__ u32 smem_u32(const void* p) {
    u32 a;
    asm("{ .reg .u64 t; cvta.to.shared.u64 t, %1; cvt.u32.u64 %0, t; }" : "=r"(a) : "l"(p));
    return a;
}
__device__ __forceinline__ void mma_bf16(float* c, const u32* a, const u32* b) {
    asm volatile("mma.sync.aligned.m16n8k16.row.col.f32.bf16.bf16.f32 "
        "{%0,%1,%2,%3}, {%4,%5,%6,%7}, {%8,%9}, {%0,%1,%2,%3};"
        : "+f"(c[0]), "+f"(c[1]), "+f"(c[2]), "+f"(c[3])
        : "r"(a[0]), "r"(a[1]), "r"(a[2]), "r"(a[3]), "r"(b[0]), "r"(b[1]));
}
__device__ __forceinline__ void ldsm4(u32* r, u32 addr) {
    asm volatile("ldmatrix.sync.aligned.m8n8.x4.shared.b16 {%0,%1,%2,%3}, [%4];"
        : "=r"(r[0]), "=r"(r[1]), "=r"(r[2]), "=r"(r[3]) : "r"(addr));
}
__device__ __forceinline__ void lds128(u32* r, u32 addr) {
    asm volatile("ld.shared.v4.u32 {%0,%1,%2,%3}, [%4];"
        : "=r"(r[0]), "=r"(r[1]), "=r"(r[2]), "=r"(r[3]) : "r"(addr));
}
__device__ __forceinline__ void cp16(u32 dst, const void* src) {
    asm volatile("cp.async.cg.shared.global [%0], [%1], 16;" :: "r"(dst), "l"(src) : "memory");
}
__device__ __forceinline__ void split_bf16(float v, u16& h, u16& l) {
    __nv_bfloat16 hb = __float2bfloat16_rn(v);
    float r = v - __bfloat162float(hb);
    h = __bfloat16_as_ushort(hb);
    l = __bfloat16_as_ushort(__float2bfloat16_rn(r));
}

// ---------------- ka1: bc, WgT, bveff, uT -------------------------------------
__global__ void __launch_bounds__(128) ka1(
    const float* __restrict__ Wt, const float* __restrict__ bt,
    const float* __restrict__ chr, const float* __restrict__ Wg,
    const float* __restrict__ Wv, const float* __restrict__ bv)
{
    int m = blockIdx.x, tid = threadIdx.x;
    int lane = tid & 31, warp = tid >> 5;
    __shared__ float red[4];

    float wv  = Wv[m * DD + tid];
    float bcv = bt[m * DD + tid] + chr[m * DD + tid];
    g_bc[m * DD + tid]  = bcv;
    g_WgT[tid * MM + m] = Wg[m * DD + tid];

    float v = bcv * wv;
    #pragma unroll
    for (int o = 16; o > 0; o >>= 1) v += __shfl_down_sync(0xffffffffu, v, o);
    if (lane == 0) red[warp] = v;
    __syncthreads();
    if (tid == 0) g_bveff[m] = bv[m] + red[0] + red[1] + red[2] + red[3];

    const float4* W4 = (const float4*)Wt + (size_t)m * 4096;
    float4 wv4 = ((const float4*)(Wv + m * DD))[lane];
    for (int r = warp; r < DD; r += 8) {
        float4 w0 = W4[r * 32 + lane];
        float4 w1 = W4[(r + 4) * 32 + lane];
        float a0 = w0.x * wv4.x + w0.y * wv4.y + w0.z * wv4.z + w0.w * wv4.w;
        float a1 = w1.x * wv4.x + w1.y * wv4.y + w1.z * wv4.z + w1.w * wv4.w;
        #pragma unroll
        for (int o = 16; o > 0; o >>= 1) {
            a0 += __shfl_down_sync(0xffffffffu, a0, o);
            a1 += __shfl_down_sync(0xffffffffu, a1, o);
        }
        if (lane == 0) {
            g_uT[r * MM + m]       = a0;
            g_uT[(r + 4) * MM + m] = a1;
        }
    }
}

// ---------------- ka2: Wtil = Wt@Wi_bot -> fragment-packed bf16 hi/lo ----------
__global__ void __launch_bounds__(128) ka2(
    const float* __restrict__ Wt, const float* __restrict__ Wi,
    const float* __restrict__ bi)
{
    int bid = blockIdx.x;
    int m = bid >> 2, dq = bid & 3, j = threadIdx.x;   // j = e
    u32* buf = g_Bpk + (size_t)m * 16384;

    float acc[32];

    if (m == 64) {   // Wi_top: B(e,d) = Wi[d][e]
        #pragma unroll 4
        for (int dd = 0; dd < 32; ++dd)
            acc[dd] = Wi[(dq * 32 + dd) * DD + j];
        if (dq == 0) g_bct[64 * DD + j] = bi[j];
    } else {
        __shared__ float ws[33][129];
        #pragma unroll
        for (int k = 0; k < 32; ++k) {
            int idx = j + k * 128;
            int d = idx >> 7, e = idx & 127;
            ws[d][e] = Wt[(size_t)(m * DD + dq * 32 + d) * DD + e];
        }
        if (dq == 0) ws[32][j] = g_bc[m * DD + j];
        __syncthreads();

        #pragma unroll
        for (int d = 0; d < 32; ++d) acc[d] = 0.f;
        float accb = 0.f;
        for (int e = 0; e < 128; ++e) {
            float wi = Wi[(128 + e) * DD + j];
            #pragma unroll
            for (int d = 0; d < 32; ++d) acc[d] = fmaf(ws[d][e], wi, acc[d]);
            if (dq == 0) accb = fmaf(ws[32][e], wi, accb);
        }
        if (dq == 0) g_bct[m * DD + j] = accb;
    }

    int ntile = j >> 3;
    #pragma unroll
    for (int dd = 0; dd < 32; dd += 2) {
        int d = dq * 32 + dd;
        u16 h0, l0, h1, l1;
        split_bf16(acc[dd], h0, l0);
        split_bf16(acc[dd + 1], h1, l1);
        u32 hw = (u32)h0 | ((u32)h1 << 16);
        u32 lw = (u32)l0 | ((u32)l1 << 16);
        int lane = (j & 7) * 4 + ((d & 7) >> 1);
        int ks = d >> 4;
        int rh = (d >> 3) & 1;
        u32* v = buf + (((ks * 16) + ntile) * 32 + lane) * 4;
        v[rh]     = hw;
        v[2 + rh] = lw;
    }
}

// ---------------- kb: selector / c / victory ----------------------------------
__global__ void __launch_bounds__(256) kb_selector(
    const float* __restrict__ x, const float* __restrict__ ctx,
    const float* __restrict__ W1, const float* __restrict__ b1,
    const float* __restrict__ W2, const float* __restrict__ b2,
    const float* __restrict__ O,  const float* __restrict__ bg,
    float* __restrict__ out)
{
    __shared__ __align__(16) float sind[256][20];   // 80B row stride: 16B-aligned rows
    __shared__ __align__(16) float hs[16][256];
    __shared__ float ls[16][64];
    __shared__ float vs[16][64];

    int t0 = blockIdx.x * 16;
    int tid = threadIdx.x;

    #pragma unroll
    for (int k = 0; k < 16; ++k) {
        int idx = tid + k * 256;
        int tok = idx >> 8, col = idx & 255;
        float v = (col < 128) ? x[(size_t)(t0 + tok) * DD + col]
                              : ctx[(size_t)(t0 + tok) * DD + (col - 128)];
        sind[col][tok] = v;
    }
    __syncthreads();

    // h = gelu(sel_in @ W1 + b1); thread owns column j; float4 LDS reads
    {
        int j = tid;
        float acc[16];
        float bj = b1[j];
        #pragma unroll
        for (int q = 0; q < 16; ++q) acc[q] = bj;
        for (int i = 0; i < 256; ++i) {
            float w = W1[i * 256 + j];
            float4 s0 = *(const float4*)&sind[i][0];
            float4 s1 = *(const float4*)&sind[i][4];
            float4 s2 = *(const float4*)&sind[i][8];
            float4 s3 = *(const float4*)&sind[i][12];
            acc[0]  = fmaf(s0.x, w, acc[0]);  acc[1]  = fmaf(s0.y, w, acc[1]);
            acc[2]  = fmaf(s0.z, w, acc[2]);  acc[3]  = fmaf(s0.w, w, acc[3]);
            acc[4]  = fmaf(s1.x, w, acc[4]);  acc[5]  = fmaf(s1.y, w, acc[5]);
            acc[6]  = fmaf(s1.z, w, acc[6]);  acc[7]  = fmaf(s1.w, w, acc[7]);
            acc[8]  = fmaf(s2.x, w, acc[8]);  acc[9]  = fmaf(s2.y, w, acc[9]);
            acc[10] = fmaf(s2.z, w, acc[10]); acc[11] = fmaf(s2.w, w, acc[11]);
            acc[12] = fmaf(s3.x, w, acc[12]); acc[13] = fmaf(s3.y, w, acc[13]);
            acc[14] = fmaf(s3.z, w, acc[14]); acc[15] = fmaf(s3.w, w, acc[15]);
        }
        #pragma unroll
        for (int q = 0; q < 16; ++q)
            hs[q][j] = 0.5f * acc[q] * (1.0f + erff(acc[q] * 0.70710678118654752f));
    }
    __syncthreads();

    int n  = tid & 63;
    int tq = tid >> 6;
    int tb = tq * 4;

    // logits = h @ W2 + b2 ; j unrolled by 4 with float4 LDS
    {
        float acc[4];
        float bn = b2[n];
        #pragma unroll
        for (int q = 0; q < 4; ++q) acc[q] = bn;
        for (int j = 0; j < 256; j += 4) {
            float w0 = W2[j * 64 + n];
            float w1 = W2[(j + 1) * 64 + n];
            float w2 = W2[(j + 2) * 64 + n];
            float w3 = W2[(j + 3) * 64 + n];
            #pragma unroll
            for (int q = 0; q < 4; ++q) {
                float4 h4 = *(const float4*)&hs[tb + q][j];
                acc[q] = fmaf(h4.x, w0, acc[q]);
                acc[q] = fmaf(h4.y, w1, acc[q]);
                acc[q] = fmaf(h4.z, w2, acc[q]);
                acc[q] = fmaf(h4.w, w3, acc[q]);
            }
        }
        #pragma unroll
        for (int q = 0; q < 4; ++q) ls[tb + q][n] = acc[q];
    }
    __syncthreads();

    if (tid < 16) {
        float mx = -1e30f;
        #pragma unroll
        for (int k = 0; k < 64; ++k) mx = fmaxf(mx, ls[tid][k]);
        float s = 0.f;
        #pragma unroll
        for (int k = 0; k < 64; ++k) { float e = expf(ls[tid][k] - mx); ls[tid][k] = e; s += e; }
        float inv = 1.0f / s;
        #pragma unroll
        for (int k = 0; k < 64; ++k) ls[tid][k] *= inv;
    }
    __syncthreads();

    {
        float ta[4], va[4], gl[4];
        float tb0 = bg[n], vb0 = g_bveff[n];
        #pragma unroll
        for (int q = 0; q < 4; ++q) { ta[q] = tb0; va[q] = vb0; gl[q] = 0.f; }
        for (int d = 0; d < DD; ++d) {
            float wg = g_WgT[d * MM + n];
            float wu = g_uT[d * MM + n];
            #pragma unroll
            for (int q = 0; q < 4; ++q) {
                float xv = sind[d][tb + q];
                ta[q] = fmaf(xv, wg, ta[q]);
                va[q] = fmaf(xv, wu, va[q]);
            }
        }
        for (int mm = 0; mm < MM; ++mm) {
            float o = O[mm * MM + n];
            #pragma unroll
            for (int q = 0; q < 4; ++q) gl[q] = fmaf(ls[tb + q][mm], o, gl[q]);
        }
        #pragma unroll
        for (int q = 0; q < 4; ++q) {
            float sc     = ls[tb + q][n];
            float timing = 1.0f / (1.0f + expf(-ta[q]));
            float vic    = 1.0f / (1.0f + expf(-va[q]));
            float gate   = 1.0f + tanhf(gl[q]);
            g_cbuf[(size_t)(t0 + tb + q) * MM + n] = timing * gate * sc;
            vs[tb + q][n] = vic * sc;
        }
    }
    __syncthreads();

    if (tid < 16) {
        float s = 0.f;
        #pragma unroll
        for (int k = 0; k < 64; ++k) s += vs[tid][k];
        out[(size_t)T_TOK * DD + t0 + tid] = s;
    }
}

// ---------------- kc: mma.sync bf16-split fused GEMM, A in registers ----------
// grid (128 token-tiles, GROUPS), 512 threads = 16 warps.
// Block tile: 64 tokens x 128 e. Warp tile 16 x 32: warp_m = wid&3, warp_n = wid>>2.
// A fragments (hi+lo, invariant over m) hoisted into 64 registers/thread.
#define APAD     136                      // bf16 elems per A row (128 + 8 pad)
#define OFF_W    0                        // 2 stages x 64KB
#define OFF_AHI  131072                   // 64*272 = 17408
#define OFF_ALO  148480
#define OFF_CS   165888                   // 13*64*4 = 3328
#define OFF_BCT  169216                   // 13*128*4 = 6656
#define SMEM_KC  175872

__global__ void __launch_bounds__(512, 1) kc_mma(const float* __restrict__ x)
{
    extern __shared__ __align__(16) char smem[];
    u32 sbase = smem_u32(smem);
    float* cs_s  = (float*)(smem + OFF_CS);
    float* bct_s = (float*)(smem + OFF_BCT);

    int tid  = threadIdx.x;
    int lane = tid & 31, wid = tid >> 5;
    int wm = wid & 3, wn = wid >> 2;
    int t0 = blockIdx.x * 64;
    int m0 = blockIdx.y * NMG;

    // c + bct tiles
    for (int i = tid; i < NMG * 64; i += 512) {
        int mi = i >> 6, r = i & 63;
        int gm = m0 + mi;
        cs_s[i] = (gm == 64) ? 1.0f : g_cbuf[(size_t)(t0 + r) * MM + gm];
    }
    for (int i = tid; i < NMG * 128; i += 512) {
        int mi = i >> 7, r = i & 127;
        bct_s[i] = g_bct[(m0 + mi) * DD + r];
    }

    // prefetch W[m0] into stage 0 (overlaps A conversion)
    {
        const char* src = (const char*)g_Bpk + (size_t)m0 * 65536;
        #pragma unroll
        for (int r = 0; r < 8; ++r) {
            int idx = tid + r * 512;
            cp16(sbase + OFF_W + idx * 16, src + (size_t)idx * 16);
        }
        asm volatile("cp.async.commit_group;" ::: "memory");
    }

    // A: convert X[64 x 128] to bf16 hi/lo in smem (padded rows)
    {
        u16* ah = (u16*)(smem + OFF_AHI);
        u16* al = (u16*)(smem + OFF_ALO);
        #pragma unroll
        for (int r = 0; r < 4; ++r) {
            int idx = tid + r * 512;
            int tok = idx >> 5, dq = idx & 31;
            float4 v = ((const float4*)(x + (size_t)(t0 + tok) * DD))[dq];
            u16 h[4], l[4];
            split_bf16(v.x, h[0], l[0]); split_bf16(v.y, h[1], l[1]);
            split_bf16(v.z, h[2], l[2]); split_bf16(v.w, h[3], l[3]);
            int o = tok * APAD + dq * 4;
            *(uint2*)&ah[o] = make_uint2((u32)h[0] | ((u32)h[1] << 16), (u32)h[2] | ((u32)h[3] << 16));
            *(uint2*)&al[o] = make_uint2((u32)l[0] | ((u32)l[1] << 16), (u32)l[2] | ((u32)l[3] << 16));
        }
    }
    __syncthreads();   // A staged, cs/bct staged

    // hoist A fragments into registers (invariant across m)
    u32 aoff = (u32)((wm * 16 + (lane & 15)) * (APAD * 2) + (lane >> 4) * 16);
    u32 Ah[8][4], Al[8][4];
    #pragma unroll
    for (int ks = 0; ks < 8; ++ks) {
        ldsm4(Ah[ks], sbase + OFF_AHI + aoff + ks * 32);
        ldsm4(Al[ks], sbase + OFF_ALO + aoff + ks * 32);
    }

    float accF[4][4];
    #pragma unroll
    for (int nt = 0; nt < 4; ++nt)
        #pragma unroll
        for (int j = 0; j < 4; ++j) accF[nt][j] = 0.f;

    int rb = wm * 16 + (lane >> 2);
    int cb = wn * 32 + 2 * (lane & 3);

    for (int mi = 0; mi < NMG; ++mi) {
        int s = mi & 1;
        if (mi + 1 < NMG) {
            const char* src = (const char*)g_Bpk + (size_t)(m0 + mi + 1) * 65536;
            u32 dst = sbase + OFF_W + (s ^ 1) * 65536;
            #pragma unroll
            for (int r = 0; r < 8; ++r) {
                int idx = tid + r * 512;
                cp16(dst + idx * 16, src + (size_t)idx * 16);
            }
            asm volatile("cp.async.commit_group;" ::: "memory");
            asm volatile("cp.async.wait_group 1;" ::: "memory");
        } else {
            asm volatile("cp.async.wait_group 0;" ::: "memory");
        }
        __syncthreads();

        float accY[4][4];
        #pragma unroll
        for (int nt = 0; nt < 4; ++nt)
            #pragma unroll
            for (int j = 0; j < 4; ++j) accY[nt][j] = 0.f;

        u32 wbase = sbase + OFF_W + s * 65536;
        #pragma unroll
        for (int ks = 0; ks < 8; ++ks) {
            #pragma unroll
            for (int nt = 0; nt < 4; ++nt) {
                u32 b4[4];
                lds128(b4, wbase + (((ks * 16) + wn * 4 + nt) * 32 + lane) * 16);
                mma_bf16(accY[nt], Ah[ks], b4);        // hi*hi
                mma_bf16(accY[nt], Ah[ks], b4 + 2);    // hi*lo
                mma_bf16(accY[nt], Al[ks], b4);        // lo*hi
            }
        }

        float c0 = cs_s[mi * 64 + rb];
        float c1 = cs_s[mi * 64 + rb + 8];
        #pragma unroll
        for (int nt = 0; nt < 4; ++nt) {
            float2 bb = *(const float2*)&bct_s[mi * 128 + cb + nt * 8];
            accF[nt][0] = fmaf(c0, accY[nt][0] + bb.x, accF[nt][0]);
            accF[nt][1] = fmaf(c0, accY[nt][1] + bb.y, accF[nt][1]);
            accF[nt][2] = fmaf(c1, accY[nt][2] + bb.x, accF[nt][2]);
            accF[nt][3] = fmaf(c1, accY[nt][3] + bb.y, accF[nt][3]);
        }
        __syncthreads();
    }

    float* part = g_part + (size_t)blockIdx.y * T_TOK * DD;
    #pragma unroll
    for (int nt = 0; nt < 4; ++nt) {
        int col = cb + nt * 8;
        *(float2*)&part[(size_t)(t0 + rb) * DD + col]     = make_float2(accF[nt][0], accF[nt][1]);
        *(float2*)&part[(size_t)(t0 + rb + 8) * DD + col] = make_float2(accF[nt][2], accF[nt][3]);
    }
}

// ---------------- kd: combine GROUPS partials ----------------------------------
__global__ void __launch_bounds__(256) kd_combine(float* __restrict__ out)
{
    int i = blockIdx.x * 256 + threadIdx.x;
    float4 r = make_float4(0.f, 0.f, 0.f, 0.f);
    #pragma unroll
    for (int g = 0; g < GROUPS; ++g) {
        float4 a = ((const float4*)(g_part + (size_t)g * T_TOK * DD))[i];
        r.x += a.x; r.y += a.y; r.z += a.z; r.w += a.w;
    }
    ((float4*)out)[i] = r;
}

// ---------------- launch ------------------------------------------------------
extern "C" void kernel_launch(void* const* d_in, const int* in_sizes, int n_in,
                              void* d_out, int out_size)
{
    const float* x    = (const float*)d_in[0];
    const float* ctx  = (const float*)d_in[1];
    const float* Wt   = (const float*)d_in[2];
    const float* bt   = (const float*)d_in[3];
    const float* chr  = (const float*)d_in[4];
    const float* Wg   = (const float*)d_in[5];
    const float* bg   = (const float*)d_in[6];
    const float* Wv   = (const float*)d_in[7];
    const float* bv   = (const float*)d_in[8];
    const float* O    = (const float*)d_in[9];
    const float* W1   = (const float*)d_in[10];
    const float* b1   = (const float*)d_in[11];
    const float* W2   = (const float*)d_in[12];
    const float* b2   = (const float*)d_in[13];
    const float* Wi   = (const float*)d_in[14];
    const float* bi   = (const float*)d_in[15];
    float* out = (float*)d_out;

    cudaFuncSetAttribute(kc_mma, cudaFuncAttributeMaxDynamicSharedMemorySize, SMEM_KC);

    ka1<<<64, 128>>>(Wt, bt, chr, Wg, Wv, bv);
    ka2<<<260, 128>>>(Wt, Wi, bi);
    kb_selector<<<T_TOK / 16, 256>>>(x, ctx, W1, b1, W2, b2, O, bg, out);
    kc_mma<<<dim3(T_TOK / 64, GROUPS), 512, SMEM_KC>>>(x);
    kd_combine<<<(T_TOK * DD / 4) / 256, 256>>>(out);
}

// round 10
// speedup vs baseline: 3.1977x; 1.0021x over previous
#include <cuda_runtime.h>
#include <cuda_bf16.h>
#include <math.h>

#define T_TOK 8192
#define DD    128
#define MM    64
#define GROUPS 5
#define NMG   13          // mechanisms per group (5*13 = 65)

typedef unsigned long long ull;
typedef unsigned int u32;
typedef unsigned short u16;

// ---------------- scratch ----------------------------------------------------
__device__ float g_cbuf[T_TOK * MM];        // c[t][m]
__device__ float g_uT[DD * MM];
__device__ float g_WgT[DD * MM];
__device__ float g_bveff[MM];
__device__ float g_bc[MM * DD];             // bt + char
__device__ float g_bct[65 * DD];            // bctil[m] ; m=64 -> bi
__device__ u32   g_Bpk[65 * 16384];         // W frag-packed: [m][ks(8)][ntile(16)][lane(32)][hi0,hi1,lo0,lo1]
__device__ float g_part[GROUPS * T_TOK * DD];

// ---------------- helpers ------------------------------------------------------
__device__ __forceinline__ u32 smem_u32(const void* p) {
    u32 a;
    asm("{ .reg .u64 t; cvta.to.shared.u64 t, %1; cvt.u32.u64 %0, t; }" : "=r"(a) : "l"(p));
    return a;
}
__device__ __forceinline__ void mma_bf16(float* c, const u32* a, const u32* b) {
    asm volatile("mma.sync.aligned.m16n8k16.row.col.f32.bf16.bf16.f32 "
        "{%0,%1,%2,%3}, {%4,%5,%6,%7}, {%8,%9}, {%0,%1,%2,%3};"
        : "+f"(c[0]), "+f"(c[1]), "+f"(c[2]), "+f"(c[3])
        : "r"(a[0]), "r"(a[1]), "r"(a[2]), "r"(a[3]), "r"(b[0]), "r"(b[1]));
}
__device__ __forceinline__ void ldsm4(u32* r, u32 addr) {
    asm volatile("ldmatrix.sync.aligned.m8n8.x4.shared.b16 {%0,%1,%2,%3}, [%4];"
        : "=r"(r[0]), "=r"(r[1]), "=r"(r[2]), "=r"(r[3]) : "r"(addr));
}
__device__ __forceinline__ void lds128(u32* r, u32 addr) {
    asm volatile("ld.shared.v4.u32 {%0,%1,%2,%3}, [%4];"
        : "=r"(r[0]), "=r"(r[1]), "=r"(r[2]), "=r"(r[3]) : "r"(addr));
}
__device__ __forceinline__ void cp16(u32 dst, const void* src) {
    asm volatile("cp.async.cg.shared.global [%0], [%1], 16;" :: "r"(dst), "l"(src) : "memory");
}
__device__ __forceinline__ void split_bf16(float v, u16& h, u16& l) {
    __nv_bfloat16 hb = __float2bfloat16_rn(v);
    float r = v - __bfloat162float(hb);
    h = __bfloat16_as_ushort(hb);
    l = __bfloat16_as_ushort(__float2bfloat16_rn(r));
}

// ---------------- ka1: bc, WgT, bveff, uT -------------------------------------
__global__ void __launch_bounds__(128) ka1(
    const float* __restrict__ Wt, const float* __restrict__ bt,
    const float* __restrict__ chr, const float* __restrict__ Wg,
    const float* __restrict__ Wv, const float* __restrict__ bv)
{
    int m = blockIdx.x, tid = threadIdx.x;
    int lane = tid & 31, warp = tid >> 5;
    __shared__ float red[4];

    float wv  = Wv[m * DD + tid];
    float bcv = bt[m * DD + tid] + chr[m * DD + tid];
    g_bc[m * DD + tid]  = bcv;
    g_WgT[tid * MM + m] = Wg[m * DD + tid];

    float v = bcv * wv;
    #pragma unroll
    for (int o = 16; o > 0; o >>= 1) v += __shfl_down_sync(0xffffffffu, v, o);
    if (lane == 0) red[warp] = v;
    __syncthreads();
    if (tid == 0) g_bveff[m] = bv[m] + red[0] + red[1] + red[2] + red[3];

    const float4* W4 = (const float4*)Wt + (size_t)m * 4096;
    float4 wv4 = ((const float4*)(Wv + m * DD))[lane];
    for (int r = warp; r < DD; r += 8) {
        float4 w0 = W4[r * 32 + lane];
        float4 w1 = W4[(r + 4) * 32 + lane];
        float a0 = w0.x * wv4.x + w0.y * wv4.y + w0.z * wv4.z + w0.w * wv4.w;
        float a1 = w1.x * wv4.x + w1.y * wv4.y + w1.z * wv4.z + w1.w * wv4.w;
        #pragma unroll
        for (int o = 16; o > 0; o >>= 1) {
            a0 += __shfl_down_sync(0xffffffffu, a0, o);
            a1 += __shfl_down_sync(0xffffffffu, a1, o);
        }
        if (lane == 0) {
            g_uT[r * MM + m]       = a0;
            g_uT[(r + 4) * MM + m] = a1;
        }
    }
}

// ---------------- ka2: Wtil = Wt@Wi_bot -> fragment-packed bf16 hi/lo ----------
__global__ void __launch_bounds__(128) ka2(
    const float* __restrict__ Wt, const float* __restrict__ Wi,
    const float* __restrict__ bi)
{
    int bid = blockIdx.x;
    int m = bid >> 2, dq = bid & 3, j = threadIdx.x;   // j = e
    u32* buf = g_Bpk + (size_t)m * 16384;

    float acc[32];

    if (m == 64) {   // Wi_top: B(e,d) = Wi[d][e]
        #pragma unroll 4
        for (int dd = 0; dd < 32; ++dd)
            acc[dd] = Wi[(dq * 32 + dd) * DD + j];
        if (dq == 0) g_bct[64 * DD + j] = bi[j];
    } else {
        __shared__ float ws[33][129];
        #pragma unroll
        for (int k = 0; k < 32; ++k) {
            int idx = j + k * 128;
            int d = idx >> 7, e = idx & 127;
            ws[d][e] = Wt[(size_t)(m * DD + dq * 32 + d) * DD + e];
        }
        if (dq == 0) ws[32][j] = g_bc[m * DD + j];
        __syncthreads();

        #pragma unroll
        for (int d = 0; d < 32; ++d) acc[d] = 0.f;
        float accb = 0.f;
        for (int e = 0; e < 128; ++e) {
            float wi = Wi[(128 + e) * DD + j];
            #pragma unroll
            for (int d = 0; d < 32; ++d) acc[d] = fmaf(ws[d][e], wi, acc[d]);
            if (dq == 0) accb = fmaf(ws[32][e], wi, accb);
        }
        if (dq == 0) g_bct[m * DD + j] = accb;
    }

    int ntile = j >> 3;
    #pragma unroll
    for (int dd = 0; dd < 32; dd += 2) {
        int d = dq * 32 + dd;
        u16 h0, l0, h1, l1;
        split_bf16(acc[dd], h0, l0);
        split_bf16(acc[dd + 1], h1, l1);
        u32 hw = (u32)h0 | ((u32)h1 << 16);
        u32 lw = (u32)l0 | ((u32)l1 << 16);
        int lane = (j & 7) * 4 + ((d & 7) >> 1);
        int ks = d >> 4;
        int rh = (d >> 3) & 1;
        u32* v = buf + (((ks * 16) + ntile) * 32 + lane) * 4;
        v[rh]     = hw;
        v[2 + rh] = lw;
    }
}

// ---------------- kb: selector / c / victory ----------------------------------
__global__ void __launch_bounds__(256) kb_selector(
    const float* __restrict__ x, const float* __restrict__ ctx,
    const float* __restrict__ W1, const float* __restrict__ b1,
    const float* __restrict__ W2, const float* __restrict__ b2,
    const float* __restrict__ O,  const float* __restrict__ bg,
    float* __restrict__ out)
{
    __shared__ __align__(16) float sind[256][20];
    __shared__ __align__(16) float hs[16][256];
    __shared__ float ls[16][64];
    __shared__ float vs[16][64];

    int t0 = blockIdx.x * 16;
    int tid = threadIdx.x;

    #pragma unroll
    for (int k = 0; k < 16; ++k) {
        int idx = tid + k * 256;
        int tok = idx >> 8, col = idx & 255;
        float v = (col < 128) ? x[(size_t)(t0 + tok) * DD + col]
                              : ctx[(size_t)(t0 + tok) * DD + (col - 128)];
        sind[col][tok] = v;
    }
    __syncthreads();

    {
        int j = tid;
        float acc[16];
        float bj = b1[j];
        #pragma unroll
        for (int q = 0; q < 16; ++q) acc[q] = bj;
        for (int i = 0; i < 256; ++i) {
            float w = W1[i * 256 + j];
            float4 s0 = *(const float4*)&sind[i][0];
            float4 s1 = *(const float4*)&sind[i][4];
            float4 s2 = *(const float4*)&sind[i][8];
            float4 s3 = *(const float4*)&sind[i][12];
            acc[0]  = fmaf(s0.x, w, acc[0]);  acc[1]  = fmaf(s0.y, w, acc[1]);
            acc[2]  = fmaf(s0.z, w, acc[2]);  acc[3]  = fmaf(s0.w, w, acc[3]);
            acc[4]  = fmaf(s1.x, w, acc[4]);  acc[5]  = fmaf(s1.y, w, acc[5]);
            acc[6]  = fmaf(s1.z, w, acc[6]);  acc[7]  = fmaf(s1.w, w, acc[7]);
            acc[8]  = fmaf(s2.x, w, acc[8]);  acc[9]  = fmaf(s2.y, w, acc[9]);
            acc[10] = fmaf(s2.z, w, acc[10]); acc[11] = fmaf(s2.w, w, acc[11]);
            acc[12] = fmaf(s3.x, w, acc[12]); acc[13] = fmaf(s3.y, w, acc[13]);
            acc[14] = fmaf(s3.z, w, acc[14]); acc[15] = fmaf(s3.w, w, acc[15]);
        }
        #pragma unroll
        for (int q = 0; q < 16; ++q)
            hs[q][j] = 0.5f * acc[q] * (1.0f + erff(acc[q] * 0.70710678118654752f));
    }
    __syncthreads();

    int n  = tid & 63;
    int tq = tid >> 6;
    int tb = tq * 4;

    {
        float acc[4];
        float bn = b2[n];
        #pragma unroll
        for (int q = 0; q < 4; ++q) acc[q] = bn;
        for (int j = 0; j < 256; j += 4) {
            float w0 = W2[j * 64 + n];
            float w1 = W2[(j + 1) * 64 + n];
            float w2 = W2[(j + 2) * 64 + n];
            float w3 = W2[(j + 3) * 64 + n];
            #pragma unroll
            for (int q = 0; q < 4; ++q) {
                float4 h4 = *(const float4*)&hs[tb + q][j];
                acc[q] = fmaf(h4.x, w0, acc[q]);
                acc[q] = fmaf(h4.y, w1, acc[q]);
                acc[q] = fmaf(h4.z, w2, acc[q]);
                acc[q] = fmaf(h4.w, w3, acc[q]);
            }
        }
        #pragma unroll
        for (int q = 0; q < 4; ++q) ls[tb + q][n] = acc[q];
    }
    __syncthreads();

    if (tid < 16) {
        float mx = -1e30f;
        #pragma unroll
        for (int k = 0; k < 64; ++k) mx = fmaxf(mx, ls[tid][k]);
        float s = 0.f;
        #pragma unroll
        for (int k = 0; k < 64; ++k) { float e = expf(ls[tid][k] - mx); ls[tid][k] = e; s += e; }
        float inv = 1.0f / s;
        #pragma unroll
        for (int k = 0; k < 64; ++k) ls[tid][k] *= inv;
    }
    __syncthreads();

    {
        float ta[4], va[4], gl[4];
        float tb0 = bg[n], vb0 = g_bveff[n];
        #pragma unroll
        for (int q = 0; q < 4; ++q) { ta[q] = tb0; va[q] = vb0; gl[q] = 0.f; }
        for (int d = 0; d < DD; ++d) {
            float wg = g_WgT[d * MM + n];
            float wu = g_uT[d * MM + n];
            #pragma unroll
            for (int q = 0; q < 4; ++q) {
                float xv = sind[d][tb + q];
                ta[q] = fmaf(xv, wg, ta[q]);
                va[q] = fmaf(xv, wu, va[q]);
            }
        }
        for (int mm = 0; mm < MM; ++mm) {
            float o = O[mm * MM + n];
            #pragma unroll
            for (int q = 0; q < 4; ++q) gl[q] = fmaf(ls[tb + q][mm], o, gl[q]);
        }
        #pragma unroll
        for (int q = 0; q < 4; ++q) {
            float sc     = ls[tb + q][n];
            float timing = 1.0f / (1.0f + expf(-ta[q]));
            float vic    = 1.0f / (1.0f + expf(-va[q]));
            float gate   = 1.0f + tanhf(gl[q]);
            g_cbuf[(size_t)(t0 + tb + q) * MM + n] = timing * gate * sc;
            vs[tb + q][n] = vic * sc;
        }
    }
    __syncthreads();

    if (tid < 16) {
        float s = 0.f;
        #pragma unroll
        for (int k = 0; k < 64; ++k) s += vs[tid][k];
        out[(size_t)T_TOK * DD + t0 + tid] = s;
    }
}

// ---------------- kc: mma.sync bf16-split fused GEMM, A in regs, ILP-ordered ---
#define APAD     136
#define OFF_W    0                        // 2 stages x 64KB
#define OFF_AHI  131072
#define OFF_ALO  148480
#define OFF_CS   165888
#define OFF_BCT  169216
#define SMEM_KC  175872

__global__ void __launch_bounds__(512, 1) kc_mma(const float* __restrict__ x)
{
    extern __shared__ __align__(16) char smem[];
    u32 sbase = smem_u32(smem);
    float* cs_s  = (float*)(smem + OFF_CS);
    float* bct_s = (float*)(smem + OFF_BCT);

    int tid  = threadIdx.x;
    int lane = tid & 31, wid = tid >> 5;
    int wm = wid & 3, wn = wid >> 2;
    int t0 = blockIdx.x * 64;
    int m0 = blockIdx.y * NMG;

    for (int i = tid; i < NMG * 64; i += 512) {
        int mi = i >> 6, r = i & 63;
        int gm = m0 + mi;
        cs_s[i] = (gm == 64) ? 1.0f : g_cbuf[(size_t)(t0 + r) * MM + gm];
    }
    for (int i = tid; i < NMG * 128; i += 512) {
        int mi = i >> 7, r = i & 127;
        bct_s[i] = g_bct[(m0 + mi) * DD + r];
    }

    // prefetch W[m0] into stage 0 (overlaps A conversion)
    {
        const char* src = (const char*)g_Bpk + (size_t)m0 * 65536;
        #pragma unroll
        for (int r = 0; r < 8; ++r) {
            int idx = tid + r * 512;
            cp16(sbase + OFF_W + idx * 16, src + (size_t)idx * 16);
        }
        asm volatile("cp.async.commit_group;" ::: "memory");
    }

    // A: convert X[64 x 128] to bf16 hi/lo in smem (padded rows)
    {
        u16* ah = (u16*)(smem + OFF_AHI);
        u16* al = (u16*)(smem + OFF_ALO);
        #pragma unroll
        for (int r = 0; r < 4; ++r) {
            int idx = tid + r * 512;
            int tok = idx >> 5, dq = idx & 31;
            float4 v = ((const float4*)(x + (size_t)(t0 + tok) * DD))[dq];
            u16 h[4], l[4];
            split_bf16(v.x, h[0], l[0]); split_bf16(v.y, h[1], l[1]);
            split_bf16(v.z, h[2], l[2]); split_bf16(v.w, h[3], l[3]);
            int o = tok * APAD + dq * 4;
            *(uint2*)&ah[o] = make_uint2((u32)h[0] | ((u32)h[1] << 16), (u32)h[2] | ((u32)h[3] << 16));
            *(uint2*)&al[o] = make_uint2((u32)l[0] | ((u32)l[1] << 16), (u32)l[2] | ((u32)l[3] << 16));
        }
    }
    __syncthreads();

    // hoist A fragments into registers (invariant across m)
    u32 aoff = (u32)((wm * 16 + (lane & 15)) * (APAD * 2) + (lane >> 4) * 16);
    u32 Ah[8][4], Al[8][4];
    #pragma unroll
    for (int ks = 0; ks < 8; ++ks) {
        ldsm4(Ah[ks], sbase + OFF_AHI + aoff + ks * 32);
        ldsm4(Al[ks], sbase + OFF_ALO + aoff + ks * 32);
    }

    float accF[4][4];
    #pragma unroll
    for (int nt = 0; nt < 4; ++nt)
        #pragma unroll
        for (int j = 0; j < 4; ++j) accF[nt][j] = 0.f;

    int rb = wm * 16 + (lane >> 2);
    int cb = wn * 32 + 2 * (lane & 3);

    for (int mi = 0; mi < NMG; ++mi) {
        int s = mi & 1;
        if (mi + 1 < NMG) {
            const char* src = (const char*)g_Bpk + (size_t)(m0 + mi + 1) * 65536;
            u32 dst = sbase + OFF_W + (s ^ 1) * 65536;
            #pragma unroll
            for (int r = 0; r < 8; ++r) {
                int idx = tid + r * 512;
                cp16(dst + idx * 16, src + (size_t)idx * 16);
            }
            asm volatile("cp.async.commit_group;" ::: "memory");
            asm volatile("cp.async.wait_group 1;" ::: "memory");
        } else {
            asm volatile("cp.async.wait_group 0;" ::: "memory");
        }
        __syncthreads();

        float accY[4][4];
        #pragma unroll
        for (int nt = 0; nt < 4; ++nt)
            #pragma unroll
            for (int j = 0; j < 4; ++j) accY[nt][j] = 0.f;

        u32 wbase = sbase + OFF_W + s * 65536;
        #pragma unroll
        for (int ks = 0; ks < 8; ++ks) {
            // load all 4 n-tiles' B fragments up front, then issue the 12
            // HMMAs term-major so consecutive MMAs hit different accumulators
            u32 b4[4][4];
            #pragma unroll
            for (int nt = 0; nt < 4; ++nt)
                lds128(b4[nt], wbase + (((ks * 16) + wn * 4 + nt) * 32 + lane) * 16);
            #pragma unroll
            for (int nt = 0; nt < 4; ++nt) mma_bf16(accY[nt], Ah[ks], b4[nt]);      // hi*hi
            #pragma unroll
            for (int nt = 0; nt < 4; ++nt) mma_bf16(accY[nt], Ah[ks], b4[nt] + 2);  // hi*lo
            #pragma unroll
            for (int nt = 0; nt < 4; ++nt) mma_bf16(accY[nt], Al[ks], b4[nt]);      // lo*hi
        }

        float c0 = cs_s[mi * 64 + rb];
        float c1 = cs_s[mi * 64 + rb + 8];
        #pragma unroll
        for (int nt = 0; nt < 4; ++nt) {
            float2 bb = *(const float2*)&bct_s[mi * 128 + cb + nt * 8];
            accF[nt][0] = fmaf(c0, accY[nt][0] + bb.x, accF[nt][0]);
            accF[nt][1] = fmaf(c0, accY[nt][1] + bb.y, accF[nt][1]);
            accF[nt][2] = fmaf(c1, accY[nt][2] + bb.x, accF[nt][2]);
            accF[nt][3] = fmaf(c1, accY[nt][3] + bb.y, accF[nt][3]);
        }
        __syncthreads();
    }

    float* part = g_part + (size_t)blockIdx.y * T_TOK * DD;
    #pragma unroll
    for (int nt = 0; nt < 4; ++nt) {
        int col = cb + nt * 8;
        *(float2*)&part[(size_t)(t0 + rb) * DD + col]     = make_float2(accF[nt][0], accF[nt][1]);
        *(float2*)&part[(size_t)(t0 + rb + 8) * DD + col] = make_float2(accF[nt][2], accF[nt][3]);
    }
}

// ---------------- kd: combine GROUPS partials ----------------------------------
__global__ void __launch_bounds__(256) kd_combine(float* __restrict__ out)
{
    int i = blockIdx.x * 256 + threadIdx.x;
    float4 r = make_float4(0.f, 0.f, 0.f, 0.f);
    #pragma unroll
    for (int g = 0; g < GROUPS; ++g) {
        float4 a = ((const float4*)(g_part + (size_t)g * T_TOK * DD))[i];
        r.x += a.x; r.y += a.y; r.z += a.z; r.w += a.w;
    }
    ((float4*)out)[i] = r;
}

// ---------------- launch ------------------------------------------------------
extern "C" void kernel_launch(void* const* d_in, const int* in_sizes, int n_in,
                              void* d_out, int out_size)
{
    const float* x    = (const float*)d_in[0];
    const float* ctx  = (const float*)d_in[1];
    const float* Wt   = (const float*)d_in[2];
    const float* bt   = (const float*)d_in[3];
    const float* chr  = (const float*)d_in[4];
    const float* Wg   = (const float*)d_in[5];
    const float* bg   = (const float*)d_in[6];
    const float* Wv   = (const float*)d_in[7];
    const float* bv   = (const float*)d_in[8];
    const float* O    = (const float*)d_in[9];
    const float* W1   = (const float*)d_in[10];
    const float* b1   = (const float*)d_in[11];
    const float* W2   = (const float*)d_in[12];
    const float* b2   = (const float*)d_in[13];
    const float* Wi   = (const float*)d_in[14];
    const float* bi   = (const float*)d_in[15];
    float* out = (float*)d_out;

    cudaFuncSetAttribute(kc_mma, cudaFuncAttributeMaxDynamicSharedMemorySize, SMEM_KC);

    ka1<<<64, 128>>>(Wt, bt, chr, Wg, Wv, bv);
    ka2<<<260, 128>>>(Wt, Wi, bi);
    kb_selector<<<T_TOK / 16, 256>>>(x, ctx, W1, b1, W2, b2, O, bg, out);
    kc_mma<<<dim3(T_TOK / 64, GROUPS), 512, SMEM_KC>>>(x);
    kd_combine<<<(T_TOK * DD / 4) / 256, 256>>>(out);
}

// round 11
// speedup vs baseline: 3.6526x; 1.1423x over previous
#include <cuda_runtime.h>
#include <cuda_bf16.h>
#include <math.h>

#define T_TOK 8192
#define DD    128
#define MM    64
#define GROUPS 5
#define NMG   13          // mechanisms per group (5*13 = 65)

typedef unsigned long long ull;
typedef unsigned int u32;
typedef unsigned short u16;

// ---------------- scratch ----------------------------------------------------
__device__ float g_cbuf[T_TOK * MM];        // c[t][m]
__device__ float g_uT[DD * MM];             // [d][m]
__device__ float g_bveff[MM];
__device__ float g_bc[MM * DD];             // bt + char
__device__ float g_bct[65 * DD];            // bctil[m] ; m=64 -> bi
__device__ u32   g_Bpk[65 * 16384];         // kc W frag-packed
__device__ u32   g_W1pk[16 * 48 * 32 * 4];  // kb extended-W frag-packed (384 cols)
__device__ float g_part[GROUPS * T_TOK * DD];

// ---------------- helpers ------------------------------------------------------
__device__ __forceinline__ u32 smem_u32(const void* p) {
    u32 a;
    asm("{ .reg .u64 t; cvta.to.shared.u64 t, %1; cvt.u32.u64 %0, t; }" : "=r"(a) : "l"(p));
    return a;
}
__device__ __forceinline__ void mma_bf16(float* c, const u32* a, const u32* b) {
    asm volatile("mma.sync.aligned.m16n8k16.row.col.f32.bf16.bf16.f32 "
        "{%0,%1,%2,%3}, {%4,%5,%6,%7}, {%8,%9}, {%0,%1,%2,%3};"
        : "+f"(c[0]), "+f"(c[1]), "+f"(c[2]), "+f"(c[3])
        : "r"(a[0]), "r"(a[1]), "r"(a[2]), "r"(a[3]), "r"(b[0]), "r"(b[1]));
}
__device__ __forceinline__ void ldsm4(u32* r, u32 addr) {
    asm volatile("ldmatrix.sync.aligned.m8n8.x4.shared.b16 {%0,%1,%2,%3}, [%4];"
        : "=r"(r[0]), "=r"(r[1]), "=r"(r[2]), "=r"(r[3]) : "r"(addr));
}
__device__ __forceinline__ void lds128(u32* r, u32 addr) {
    asm volatile("ld.shared.v4.u32 {%0,%1,%2,%3}, [%4];"
        : "=r"(r[0]), "=r"(r[1]), "=r"(r[2]), "=r"(r[3]) : "r"(addr));
}
__device__ __forceinline__ void cp16(u32 dst, const void* src) {
    asm volatile("cp.async.cg.shared.global [%0], [%1], 16;" :: "r"(dst), "l"(src) : "memory");
}
__device__ __forceinline__ void split_bf16(float v, u16& h, u16& l) {
    __nv_bfloat16 hb = __float2bfloat16_rn(v);
    float r = v - __bfloat162float(hb);
    h = __bfloat16_as_ushort(hb);
    l = __bfloat16_as_ushort(__float2bfloat16_rn(r));
}

// ---------------- ka1: bc, bveff, uT --------------------------------------------
__global__ void __launch_bounds__(128) ka1(
    const float* __restrict__ Wt, const float* __restrict__ bt,
    const float* __restrict__ chr,
    const float* __restrict__ Wv, const float* __restrict__ bv)
{
    int m = blockIdx.x, tid = threadIdx.x;
    int lane = tid & 31, warp = tid >> 5;
    __shared__ float red[4];

    float wv  = Wv[m * DD + tid];
    float bcv = bt[m * DD + tid] + chr[m * DD + tid];
    g_bc[m * DD + tid]  = bcv;

    float v = bcv * wv;
    #pragma unroll
    for (int o = 16; o > 0; o >>= 1) v += __shfl_down_sync(0xffffffffu, v, o);
    if (lane == 0) red[warp] = v;
    __syncthreads();
    if (tid == 0) g_bveff[m] = bv[m] + red[0] + red[1] + red[2] + red[3];

    const float4* W4 = (const float4*)Wt + (size_t)m * 4096;
    float4 wv4 = ((const float4*)(Wv + m * DD))[lane];
    for (int r = warp; r < DD; r += 8) {
        float4 w0 = W4[r * 32 + lane];
        float4 w1 = W4[(r + 4) * 32 + lane];
        float a0 = w0.x * wv4.x + w0.y * wv4.y + w0.z * wv4.z + w0.w * wv4.w;
        float a1 = w1.x * wv4.x + w1.y * wv4.y + w1.z * wv4.z + w1.w * wv4.w;
        #pragma unroll
        for (int o = 16; o > 0; o >>= 1) {
            a0 += __shfl_down_sync(0xffffffffu, a0, o);
            a1 += __shfl_down_sync(0xffffffffu, a1, o);
        }
        if (lane == 0) {
            g_uT[r * MM + m]       = a0;
            g_uT[(r + 4) * MM + m] = a1;
        }
    }
}

// ---------------- ka2: Wtil = Wt@Wi_bot -> fragment-packed bf16 hi/lo ----------
__global__ void __launch_bounds__(128) ka2(
    const float* __restrict__ Wt, const float* __restrict__ Wi,
    const float* __restrict__ bi)
{
    int bid = blockIdx.x;
    int m = bid >> 2, dq = bid & 3, j = threadIdx.x;   // j = e
    u32* buf = g_Bpk + (size_t)m * 16384;

    float acc[32];

    if (m == 64) {   // Wi_top: B(e,d) = Wi[d][e]
        #pragma unroll 4
        for (int dd = 0; dd < 32; ++dd)
            acc[dd] = Wi[(dq * 32 + dd) * DD + j];
        if (dq == 0) g_bct[64 * DD + j] = bi[j];
    } else {
        __shared__ float ws[33][129];
        #pragma unroll
        for (int k = 0; k < 32; ++k) {
            int idx = j + k * 128;
            int d = idx >> 7, e = idx & 127;
            ws[d][e] = Wt[(size_t)(m * DD + dq * 32 + d) * DD + e];
        }
        if (dq == 0) ws[32][j] = g_bc[m * DD + j];
        __syncthreads();

        #pragma unroll
        for (int d = 0; d < 32; ++d) acc[d] = 0.f;
        float accb = 0.f;
        for (int e = 0; e < 128; ++e) {
            float wi = Wi[(128 + e) * DD + j];
            #pragma unroll
            for (int d = 0; d < 32; ++d) acc[d] = fmaf(ws[d][e], wi, acc[d]);
            if (dq == 0) accb = fmaf(ws[32][e], wi, accb);
        }
        if (dq == 0) g_bct[m * DD + j] = accb;
    }

    int ntile = j >> 3;
    #pragma unroll
    for (int dd = 0; dd < 32; dd += 2) {
        int d = dq * 32 + dd;
        u16 h0, l0, h1, l1;
        split_bf16(acc[dd], h0, l0);
        split_bf16(acc[dd + 1], h1, l1);
        u32 hw = (u32)h0 | ((u32)h1 << 16);
        u32 lw = (u32)l0 | ((u32)l1 << 16);
        int lane = (j & 7) * 4 + ((d & 7) >> 1);
        int ks = d >> 4;
        int rh = (d >> 3) & 1;
        u32* v = buf + (((ks * 16) + ntile) * 32 + lane) * 4;
        v[rh]     = hw;
        v[2 + rh] = lw;
    }
}

// ---------------- ka3: pack extended W1 [256k x 384n] into frags ----------------
// cols 0..255: W1 ; 256..319: Wg (zero for k>=128) ; 320..383: u (zero for k>=128)
__global__ void __launch_bounds__(128) ka3(
    const float* __restrict__ W1, const float* __restrict__ Wg)
{
    int j = blockIdx.x;        // col 0..383
    int t = threadIdx.x;       // handles k = 2t, 2t+1
    float v0, v1;
    if (j < 256)      { v0 = W1[(2 * t) * 256 + j]; v1 = W1[(2 * t + 1) * 256 + j]; }
    else if (j < 320) {
        int g = j - 256;
        v0 = (t < 64) ? Wg[g * DD + 2 * t]     : 0.f;
        v1 = (t < 64) ? Wg[g * DD + 2 * t + 1] : 0.f;
    } else {
        int g = j - 320;
        v0 = (t < 64) ? g_uT[(2 * t) * MM + g]     : 0.f;
        v1 = (t < 64) ? g_uT[(2 * t + 1) * MM + g] : 0.f;
    }
    u16 h0, l0, h1, l1;
    split_bf16(v0, h0, l0);
    split_bf16(v1, h1, l1);
    u32 hw = (u32)h0 | ((u32)h1 << 16);
    u32 lw = (u32)l0 | ((u32)l1 << 16);
    int lane = (j & 7) * 4 + (t & 3);
    int ks = t >> 3;
    int rh = (t >> 2) & 1;
    int nt = j >> 3;
    u32* v = g_W1pk + (((ks * 48) + nt) * 32 + lane) * 4;
    v[rh]     = hw;
    v[2 + rh] = lw;
}

// ---------------- kb: tensor-core selector / c / victory ------------------------
// grid 128, 512 threads. 64 tokens/CTA. MMA over k=256, N=384 (h|ta|va).
#define KB_OFF_A    0                    // A hi (64 x 264 u16) then lo
#define KB_ALO      33792
#define KB_OFF_B    67584                // 2 stages x 24576
#define KB_BSTG     24576
#define KB_BUFSTR   388                  // fp32 buf row stride (floats), aliases A+B
#define KB_OFF_LS   116736               // 64 x 68 fp32
#define KB_OFF_VS   134144               // 64 x 68 fp32
#define KB_OFF_BIAS 151552               // 384 fp32
#define SMEM_KB     153088

__global__ void __launch_bounds__(512, 1) kb_mma(
    const float* __restrict__ x, const float* __restrict__ ctx,
    const float* __restrict__ W2, const float* __restrict__ b2,
    const float* __restrict__ O,  const float* __restrict__ b1,
    const float* __restrict__ bg, float* __restrict__ out)
{
    extern __shared__ __align__(16) char smem[];
    u32 sbase = smem_u32(smem);
    int tid  = threadIdx.x;
    int lane = tid & 31, wid = tid >> 5;
    int wm = wid & 3, wn = wid >> 2;
    int t0 = blockIdx.x * 64;

    // bias vector
    float* bias = (float*)(smem + KB_OFF_BIAS);
    if (tid < 384) {
        float b;
        if (tid < 256)      b = b1[tid];
        else if (tid < 320) b = bg[tid - 256];
        else                b = g_bveff[tid - 320];
        bias[tid] = b;
    }

    // prefetch B ks0
    {
        const char* src = (const char*)g_W1pk;
        #pragma unroll
        for (int r = 0; r < 3; ++r)
            cp16(sbase + KB_OFF_B + (tid + r * 512) * 16, src + (size_t)(tid + r * 512) * 16);
        asm volatile("cp.async.commit_group;" ::: "memory");
    }

    // A = concat(x,ctx) split bf16 hi/lo (row stride 264 u16 = 528B)
    {
        u16* ah = (u16*)(smem + KB_OFF_A);
        u16* al = (u16*)(smem + KB_OFF_A + KB_ALO);
        #pragma unroll
        for (int r = 0; r < 8; ++r) {
            int idx = tid + r * 512;
            int tok = idx >> 6, cq = idx & 63;
            float4 v = (cq < 32) ? ((const float4*)(x   + (size_t)(t0 + tok) * DD))[cq]
                                 : ((const float4*)(ctx + (size_t)(t0 + tok) * DD))[cq - 32];
            u16 h[4], l[4];
            split_bf16(v.x, h[0], l[0]); split_bf16(v.y, h[1], l[1]);
            split_bf16(v.z, h[2], l[2]); split_bf16(v.w, h[3], l[3]);
            int o = tok * 264 + cq * 4;
            *(uint2*)&ah[o] = make_uint2((u32)h[0] | ((u32)h[1] << 16), (u32)h[2] | ((u32)h[3] << 16));
            *(uint2*)&al[o] = make_uint2((u32)l[0] | ((u32)l[1] << 16), (u32)l[2] | ((u32)l[3] << 16));
        }
    }
    __syncthreads();

    float accY[12][4];
    #pragma unroll
    for (int t = 0; t < 12; ++t)
        #pragma unroll
        for (int q = 0; q < 4; ++q) accY[t][q] = 0.f;

    u32 abyte = (u32)((wm * 16 + (lane & 15)) * 528 + (lane >> 4) * 16);

    for (int ks = 0; ks < 16; ++ks) {
        int s = ks & 1;
        if (ks < 15) {
            const char* src = (const char*)g_W1pk + (size_t)(ks + 1) * KB_BSTG;
            u32 dst = sbase + KB_OFF_B + (s ^ 1) * KB_BSTG;
            #pragma unroll
            for (int r = 0; r < 3; ++r)
                cp16(dst + (tid + r * 512) * 16, src + (size_t)(tid + r * 512) * 16);
            asm volatile("cp.async.commit_group;" ::: "memory");
            asm volatile("cp.async.wait_group 1;" ::: "memory");
        } else {
            asm volatile("cp.async.wait_group 0;" ::: "memory");
        }
        __syncthreads();

        u32 ahf[4], alf[4];
        ldsm4(ahf, sbase + KB_OFF_A + abyte + ks * 32);
        ldsm4(alf, sbase + KB_OFF_A + KB_ALO + abyte + ks * 32);
        u32 bb = sbase + KB_OFF_B + s * KB_BSTG;
        #pragma unroll
        for (int t = 0; t < 12; ++t) {
            u32 b4[4];
            lds128(b4, bb + (u32)(((wn * 12 + t) * 32 + lane) * 16));
            mma_bf16(accY[t], ahf, b4);
            mma_bf16(accY[t], ahf, b4 + 2);
            mma_bf16(accY[t], alf, b4);
        }
        __syncthreads();
    }

    // epilogue: bias + activation -> fp32 buf (aliases A+B regions)
    float* buf = (float*)smem;
    int rb = wm * 16 + (lane >> 2);
    #pragma unroll
    for (int t = 0; t < 12; ++t) {
        int col = (wn * 12 + t) * 8 + 2 * (lane & 3);
        float b0 = bias[col], b1v = bias[col + 1];
        float v00 = accY[t][0] + b0, v01 = accY[t][1] + b1v;
        float v10 = accY[t][2] + b0, v11 = accY[t][3] + b1v;
        if (col < 256) {   // GELU (whole pair is on same side: cols pair within same region)
            v00 = 0.5f * v00 * (1.0f + erff(v00 * 0.70710678118654752f));
            v01 = 0.5f * v01 * (1.0f + erff(v01 * 0.70710678118654752f));
            v10 = 0.5f * v10 * (1.0f + erff(v10 * 0.70710678118654752f));
            v11 = 0.5f * v11 * (1.0f + erff(v11 * 0.70710678118654752f));
        } else {           // sigmoid (timing / victory pre-activations)
            v00 = 1.0f / (1.0f + expf(-v00));
            v01 = 1.0f / (1.0f + expf(-v01));
            v10 = 1.0f / (1.0f + expf(-v10));
            v11 = 1.0f / (1.0f + expf(-v11));
        }
        buf[rb * KB_BUFSTR + col]           = v00;
        buf[rb * KB_BUFSTR + col + 1]       = v01;
        buf[(rb + 8) * KB_BUFSTR + col]     = v10;
        buf[(rb + 8) * KB_BUFSTR + col + 1] = v11;
    }
    __syncthreads();

    // W2: logits = gelu_h @ W2 + b2 (scalar)
    float* lsf = (float*)(smem + KB_OFF_LS);
    int n  = tid & 63;
    int tg = tid >> 6;           // 8 token groups x 8 tokens
    {
        float lg[8];
        float bn = b2[n];
        #pragma unroll
        for (int q = 0; q < 8; ++q) lg[q] = bn;
        for (int j = 0; j < 256; j += 4) {
            float w0 = W2[j * 64 + n];
            float w1 = W2[(j + 1) * 64 + n];
            float w2 = W2[(j + 2) * 64 + n];
            float w3 = W2[(j + 3) * 64 + n];
            #pragma unroll
            for (int q = 0; q < 8; ++q) {
                float4 h4 = *(const float4*)&buf[(tg * 8 + q) * KB_BUFSTR + j];
                lg[q] = fmaf(h4.x, w0, lg[q]);
                lg[q] = fmaf(h4.y, w1, lg[q]);
                lg[q] = fmaf(h4.z, w2, lg[q]);
                lg[q] = fmaf(h4.w, w3, lg[q]);
            }
        }
        #pragma unroll
        for (int q = 0; q < 8; ++q) lsf[(tg * 8 + q) * 68 + n] = lg[q];
    }
    __syncthreads();

    // softmax (one thread per token)
    if (tid < 64) {
        float* row = lsf + tid * 68;
        float mx = -1e30f;
        #pragma unroll
        for (int k = 0; k < 64; ++k) mx = fmaxf(mx, row[k]);
        float s = 0.f;
        #pragma unroll
        for (int k = 0; k < 64; ++k) { float e = expf(row[k] - mx); row[k] = e; s += e; }
        float inv = 1.0f / s;
        #pragma unroll
        for (int k = 0; k < 64; ++k) row[k] *= inv;
    }
    __syncthreads();

    // gates / c / victory
    float* vsf = (float*)(smem + KB_OFF_VS);
    {
        float gl[8];
        #pragma unroll
        for (int q = 0; q < 8; ++q) gl[q] = 0.f;
        for (int mm = 0; mm < 64; ++mm) {
            float o = O[mm * 64 + n];
            #pragma unroll
            for (int q = 0; q < 8; ++q)
                gl[q] = fmaf(lsf[(tg * 8 + q) * 68 + mm], o, gl[q]);
        }
        #pragma unroll
        for (int q = 0; q < 8; ++q) {
            int tok = tg * 8 + q;
            float sc     = lsf[tok * 68 + n];
            float timing = buf[tok * KB_BUFSTR + 256 + n];
            float vic    = buf[tok * KB_BUFSTR + 320 + n];
            float gate   = 1.0f + tanhf(gl[q]);
            g_cbuf[(size_t)(t0 + tok) * MM + n] = timing * gate * sc;
            vsf[tok * 68 + n] = vic * sc;
        }
    }
    __syncthreads();

    if (tid < 64) {
        float s = 0.f;
        #pragma unroll
        for (int k = 0; k < 64; ++k) s += vsf[tid * 68 + k];
        out[(size_t)T_TOK * DD + t0 + tid] = s;
    }
}

// ---------------- kc: mma.sync bf16-split fused GEMM (unchanged from R10) ------
#define APAD     136
#define OFF_W    0
#define OFF_AHI  131072
#define OFF_ALO  148480
#define OFF_CS   165888
#define OFF_BCT  169216
#define SMEM_KC  175872

__global__ void __launch_bounds__(512, 1) kc_mma(const float* __restrict__ x)
{
    extern __shared__ __align__(16) char smem[];
    u32 sbase = smem_u32(smem);
    float* cs_s  = (float*)(smem + OFF_CS);
    float* bct_s = (float*)(smem + OFF_BCT);

    int tid  = threadIdx.x;
    int lane = tid & 31, wid = tid >> 5;
    int wm = wid & 3, wn = wid >> 2;
    int t0 = blockIdx.x * 64;
    int m0 = blockIdx.y * NMG;

    for (int i = tid; i < NMG * 64; i += 512) {
        int mi = i >> 6, r = i & 63;
        int gm = m0 + mi;
        cs_s[i] = (gm == 64) ? 1.0f : g_cbuf[(size_t)(t0 + r) * MM + gm];
    }
    for (int i = tid; i < NMG * 128; i += 512) {
        int mi = i >> 7, r = i & 127;
        bct_s[i] = g_bct[(m0 + mi) * DD + r];
    }

    {
        const char* src = (const char*)g_Bpk + (size_t)m0 * 65536;
        #pragma unroll
        for (int r = 0; r < 8; ++r) {
            int idx = tid + r * 512;
            cp16(sbase + OFF_W + idx * 16, src + (size_t)idx * 16);
        }
        asm volatile("cp.async.commit_group;" ::: "memory");
    }

    {
        u16* ah = (u16*)(smem + OFF_AHI);
        u16* al = (u16*)(smem + OFF_ALO);
        #pragma unroll
        for (int r = 0; r < 4; ++r) {
            int idx = tid + r * 512;
            int tok = idx >> 5, dq = idx & 31;
            float4 v = ((const float4*)(x + (size_t)(t0 + tok) * DD))[dq];
            u16 h[4], l[4];
            split_bf16(v.x, h[0], l[0]); split_bf16(v.y, h[1], l[1]);
            split_bf16(v.z, h[2], l[2]); split_bf16(v.w, h[3], l[3]);
            int o = tok * APAD + dq * 4;
            *(uint2*)&ah[o] = make_uint2((u32)h[0] | ((u32)h[1] << 16), (u32)h[2] | ((u32)h[3] << 16));
            *(uint2*)&al[o] = make_uint2((u32)l[0] | ((u32)l[1] << 16), (u32)l[2] | ((u32)l[3] << 16));
        }
    }
    __syncthreads();

    u32 aoff = (u32)((wm * 16 + (lane & 15)) * (APAD * 2) + (lane >> 4) * 16);
    u32 Ah[8][4], Al[8][4];
    #pragma unroll
    for (int ks = 0; ks < 8; ++ks) {
        ldsm4(Ah[ks], sbase + OFF_AHI + aoff + ks * 32);
        ldsm4(Al[ks], sbase + OFF_ALO + aoff + ks * 32);
    }

    float accF[4][4];
    #pragma unroll
    for (int nt = 0; nt < 4; ++nt)
        #pragma unroll
        for (int j = 0; j < 4; ++j) accF[nt][j] = 0.f;

    int rb = wm * 16 + (lane >> 2);
    int cb = wn * 32 + 2 * (lane & 3);

    for (int mi = 0; mi < NMG; ++mi) {
        int s = mi & 1;
        if (mi + 1 < NMG) {
            const char* src = (const char*)g_Bpk + (size_t)(m0 + mi + 1) * 65536;
            u32 dst = sbase + OFF_W + (s ^ 1) * 65536;
            #pragma unroll
            for (int r = 0; r < 8; ++r) {
                int idx = tid + r * 512;
                cp16(dst + idx * 16, src + (size_t)idx * 16);
            }
            asm volatile("cp.async.commit_group;" ::: "memory");
            asm volatile("cp.async.wait_group 1;" ::: "memory");
        } else {
            asm volatile("cp.async.wait_group 0;" ::: "memory");
        }
        __syncthreads();

        float accY[4][4];
        #pragma unroll
        for (int nt = 0; nt < 4; ++nt)
            #pragma unroll
            for (int j = 0; j < 4; ++j) accY[nt][j] = 0.f;

        u32 wbase = sbase + OFF_W + s * 65536;
        #pragma unroll
        for (int ks = 0; ks < 8; ++ks) {
            u32 b4[4][4];
            #pragma unroll
            for (int nt = 0; nt < 4; ++nt)
                lds128(b4[nt], wbase + (((ks * 16) + wn * 4 + nt) * 32 + lane) * 16);
            #pragma unroll
            for (int nt = 0; nt < 4; ++nt) mma_bf16(accY[nt], Ah[ks], b4[nt]);
            #pragma unroll
            for (int nt = 0; nt < 4; ++nt) mma_bf16(accY[nt], Ah[ks], b4[nt] + 2);
            #pragma unroll
            for (int nt = 0; nt < 4; ++nt) mma_bf16(accY[nt], Al[ks], b4[nt]);
        }

        float c0 = cs_s[mi * 64 + rb];
        float c1 = cs_s[mi * 64 + rb + 8];
        #pragma unroll
        for (int nt = 0; nt < 4; ++nt) {
            float2 bb = *(const float2*)&bct_s[mi * 128 + cb + nt * 8];
            accF[nt][0] = fmaf(c0, accY[nt][0] + bb.x, accF[nt][0]);
            accF[nt][1] = fmaf(c0, accY[nt][1] + bb.y, accF[nt][1]);
            accF[nt][2] = fmaf(c1, accY[nt][2] + bb.x, accF[nt][2]);
            accF[nt][3] = fmaf(c1, accY[nt][3] + bb.y, accF[nt][3]);
        }
        __syncthreads();
    }

    float* part = g_part + (size_t)blockIdx.y * T_TOK * DD;
    #pragma unroll
    for (int nt = 0; nt < 4; ++nt) {
        int col = cb + nt * 8;
        *(float2*)&part[(size_t)(t0 + rb) * DD + col]     = make_float2(accF[nt][0], accF[nt][1]);
        *(float2*)&part[(size_t)(t0 + rb + 8) * DD + col] = make_float2(accF[nt][2], accF[nt][3]);
    }
}

// ---------------- kd: combine GROUPS partials ----------------------------------
__global__ void __launch_bounds__(256) kd_combine(float* __restrict__ out)
{
    int i = blockIdx.x * 256 + threadIdx.x;
    float4 r = make_float4(0.f, 0.f, 0.f, 0.f);
    #pragma unroll
    for (int g = 0; g < GROUPS; ++g) {
        float4 a = ((const float4*)(g_part + (size_t)g * T_TOK * DD))[i];
        r.x += a.x; r.y += a.y; r.z += a.z; r.w += a.w;
    }
    ((float4*)out)[i] = r;
}

// ---------------- launch ------------------------------------------------------
extern "C" void kernel_launch(void* const* d_in, const int* in_sizes, int n_in,
                              void* d_out, int out_size)
{
    const float* x    = (const float*)d_in[0];
    const float* ctx  = (const float*)d_in[1];
    const float* Wt   = (const float*)d_in[2];
    const float* bt   = (const float*)d_in[3];
    const float* chr  = (const float*)d_in[4];
    const float* Wg   = (const float*)d_in[5];
    const float* bg   = (const float*)d_in[6];
    const float* Wv   = (const float*)d_in[7];
    const float* bv   = (const float*)d_in[8];
    const float* O    = (const float*)d_in[9];
    const float* W1   = (const float*)d_in[10];
    const float* b1   = (const float*)d_in[11];
    const float* W2   = (const float*)d_in[12];
    const float* b2   = (const float*)d_in[13];
    const float* Wi   = (const float*)d_in[14];
    const float* bi   = (const float*)d_in[15];
    float* out = (float*)d_out;

    cudaFuncSetAttribute(kc_mma, cudaFuncAttributeMaxDynamicSharedMemorySize, SMEM_KC);
    cudaFuncSetAttribute(kb_mma, cudaFuncAttributeMaxDynamicSharedMemorySize, SMEM_KB);

    ka1<<<64, 128>>>(Wt, bt, chr, Wv, bv);
    ka2<<<260, 128>>>(Wt, Wi, bi);
    ka3<<<384, 128>>>(W1, Wg);
    kb_mma<<<128, 512, SMEM_KB>>>(x, ctx, W2, b2, O, b1, bg, out);
    kc_mma<<<dim3(T_TOK / 64, GROUPS), 512, SMEM_KC>>>(x);
    kd_combine<<<(T_TOK * DD / 4) / 256, 256>>>(out);
}